// round 7
// baseline (speedup 1.0000x reference)
#include <cuda_runtime.h>
#include <cuda_bf16.h>
#include <cuda_fp16.h>
#include <cstdint>

// ===========================================================================
// GQA layer, sm_103 baseline-PTX path: mma.sync (HMMA) everywhere.
//   - projections: bf16 split-2 GEMM, CTA tile 128x128 (4 warps, 64x64 each),
//       3-stage cp.async, 2 CTAs/SM, Q+K+V fused into one launch
//   - attention:   fp16 FA-2, q-tile 128/CTA, 8 warps (16 rows each),
//       2 CTAs/SM, bf16-split output
// ===========================================================================

#define S_LEN   2048
#define D_MODEL 2048
#define H_Q     32
#define KV_W    512
#define GK      2048
#define QSCALE  0.1803368801111244f   // 0.125 * log2(e)

// ------------------------------ scratch ------------------------------------
__device__ __align__(16) __half g_qh[S_LEN * D_MODEL];
__device__ __align__(16) __half g_kh[S_LEN * KV_W];
__device__ __align__(16) __half g_vh[S_LEN * KV_W];

__device__ __align__(16) __nv_bfloat16 g_ahi[S_LEN * D_MODEL];
__device__ __align__(16) __nv_bfloat16 g_alo[S_LEN * D_MODEL];
__device__ __align__(16) __nv_bfloat16 g_bhi[S_LEN * D_MODEL];
__device__ __align__(16) __nv_bfloat16 g_blo[S_LEN * D_MODEL];
__device__ __align__(16) __nv_bfloat16 g_chi[S_LEN * D_MODEL];
__device__ __align__(16) __nv_bfloat16 g_clo[S_LEN * D_MODEL];

__device__ __align__(16) __nv_bfloat16 g_wq_hi[D_MODEL * GK];
__device__ __align__(16) __nv_bfloat16 g_wq_lo[D_MODEL * GK];
__device__ __align__(16) __nv_bfloat16 g_wk_hi[KV_W * GK];
__device__ __align__(16) __nv_bfloat16 g_wk_lo[KV_W * GK];
__device__ __align__(16) __nv_bfloat16 g_wv_hi[KV_W * GK];
__device__ __align__(16) __nv_bfloat16 g_wv_lo[KV_W * GK];
__device__ __align__(16) __nv_bfloat16 g_wo_hi[D_MODEL * GK];
__device__ __align__(16) __nv_bfloat16 g_wo_lo[D_MODEL * GK];

// ------------------------------ helpers ------------------------------------
__device__ __forceinline__ uint32_t smem_u32(const void* p) {
    uint32_t a;
    asm("{ .reg .u64 t; cvta.to.shared.u64 t, %1; cvt.u32.u64 %0, t; }"
        : "=r"(a) : "l"(p));
    return a;
}

#define CP16(dst, src) \
    asm volatile("cp.async.cg.shared.global [%0], [%1], 16;" \
                 :: "r"(dst), "l"(src))
#define CPCOMMIT() asm volatile("cp.async.commit_group;" ::: "memory")
#define CPWAIT(n)  asm volatile("cp.async.wait_group %0;" :: "n"(n) : "memory")

__device__ __forceinline__ void ldsm_x4(uint32_t& r0, uint32_t& r1,
                                        uint32_t& r2, uint32_t& r3, uint32_t a) {
    asm volatile("ldmatrix.sync.aligned.m8n8.x4.shared.b16 {%0,%1,%2,%3}, [%4];"
                 : "=r"(r0), "=r"(r1), "=r"(r2), "=r"(r3) : "r"(a));
}
__device__ __forceinline__ void ldsm_x4t(uint32_t& r0, uint32_t& r1,
                                         uint32_t& r2, uint32_t& r3, uint32_t a) {
    asm volatile("ldmatrix.sync.aligned.m8n8.x4.trans.shared.b16 {%0,%1,%2,%3}, [%4];"
                 : "=r"(r0), "=r"(r1), "=r"(r2), "=r"(r3) : "r"(a));
}

__device__ __forceinline__ void mma_bf16(float* c, const uint32_t* a,
                                         uint32_t b0, uint32_t b1) {
    asm volatile("mma.sync.aligned.m16n8k16.row.col.f32.bf16.bf16.f32 "
                 "{%0,%1,%2,%3}, {%4,%5,%6,%7}, {%8,%9}, {%0,%1,%2,%3};"
                 : "+f"(c[0]), "+f"(c[1]), "+f"(c[2]), "+f"(c[3])
                 : "r"(a[0]), "r"(a[1]), "r"(a[2]), "r"(a[3]), "r"(b0), "r"(b1));
}
__device__ __forceinline__ void mma_f16(float* c, const uint32_t* a,
                                        uint32_t b0, uint32_t b1) {
    asm volatile("mma.sync.aligned.m16n8k16.row.col.f32.f16.f16.f32 "
                 "{%0,%1,%2,%3}, {%4,%5,%6,%7}, {%8,%9}, {%0,%1,%2,%3};"
                 : "+f"(c[0]), "+f"(c[1]), "+f"(c[2]), "+f"(c[3])
                 : "r"(a[0]), "r"(a[1]), "r"(a[2]), "r"(a[3]), "r"(b0), "r"(b1));
}

// ---------------------------------------------------------------------------
// asplit3
// ---------------------------------------------------------------------------
__global__ __launch_bounds__(256)
void asplit3(const float4* __restrict__ Q, const float4* __restrict__ K,
             const float4* __restrict__ V,
             __nv_bfloat16* __restrict__ ahi, __nv_bfloat16* __restrict__ alo,
             __nv_bfloat16* __restrict__ bhi, __nv_bfloat16* __restrict__ blo,
             __nv_bfloat16* __restrict__ chi, __nv_bfloat16* __restrict__ clo)
{
    const int z = blockIdx.y;
    const float4* A;  __nv_bfloat16 *hi, *lo;
    if      (z == 0) { A = Q; hi = ahi; lo = alo; }
    else if (z == 1) { A = K; hi = bhi; lo = blo; }
    else             { A = V; hi = chi; lo = clo; }

    const int i = blockIdx.x * 256 + threadIdx.x;
    float4 v = A[i];
    __nv_bfloat162 h0 = __floats2bfloat162_rn(v.x, v.y);
    __nv_bfloat162 h1 = __floats2bfloat162_rn(v.z, v.w);
    __nv_bfloat162 l0 = __floats2bfloat162_rn(v.x - __bfloat162float(h0.x),
                                              v.y - __bfloat162float(h0.y));
    __nv_bfloat162 l1 = __floats2bfloat162_rn(v.z - __bfloat162float(h1.x),
                                              v.w - __bfloat162float(h1.y));
    uint2 uh = make_uint2(*(uint32_t*)&h0, *(uint32_t*)&h1);
    uint2 ul = make_uint2(*(uint32_t*)&l0, *(uint32_t*)&l1);
    *(uint2*)(hi + (size_t)i * 4) = uh;
    *(uint2*)(lo + (size_t)i * 4) = ul;
}

// ---------------------------------------------------------------------------
// wsplit4
// ---------------------------------------------------------------------------
__global__ __launch_bounds__(256)
void wsplit4(const float* __restrict__ Wq, const float* __restrict__ Wk,
             const float* __restrict__ Wv, const float* __restrict__ Wo,
             __nv_bfloat16* __restrict__ qhi, __nv_bfloat16* __restrict__ qlo,
             __nv_bfloat16* __restrict__ khi, __nv_bfloat16* __restrict__ klo,
             __nv_bfloat16* __restrict__ vhi, __nv_bfloat16* __restrict__ vlo,
             __nv_bfloat16* __restrict__ ohi, __nv_bfloat16* __restrict__ olo)
{
    __shared__ float tile[32][33];
    const int z = blockIdx.z;
    const float* W;  __nv_bfloat16 *hi, *lo;  int Ncols;
    if      (z == 0) { W = Wq; hi = qhi; lo = qlo; Ncols = D_MODEL; }
    else if (z == 1) { W = Wk; hi = khi; lo = klo; Ncols = KV_W; }
    else if (z == 2) { W = Wv; hi = vhi; lo = vlo; Ncols = KV_W; }
    else             { W = Wo; hi = ohi; lo = olo; Ncols = D_MODEL; }

    const int bx = blockIdx.x, by = blockIdx.y;
    if (bx * 32 >= Ncols) return;
    const int tx = threadIdx.x & 31, ty = threadIdx.x >> 5;

    #pragma unroll
    for (int i = 0; i < 32; i += 8)
        tile[ty + i][tx] = W[(size_t)(by * 32 + ty + i) * Ncols + bx * 32 + tx];
    __syncthreads();
    #pragma unroll
    for (int i = 0; i < 32; i += 8) {
        const int n = bx * 32 + ty + i;
        const int k = by * 32 + tx;
        float x = tile[tx][ty + i];
        __nv_bfloat16 h = __float2bfloat16_rn(x);
        hi[(size_t)n * GK + k] = h;
        lo[(size_t)n * GK + k] = __float2bfloat16_rn(x - __bfloat162float(h));
    }
}

// ---------------------------------------------------------------------------
// GEMM body (unchanged from R6): 128x128 tile, 4 warps, 3-stage, 2 CTA/SM
// ---------------------------------------------------------------------------
#define GSTAGE 32768

template <int MODE>
__device__ __forceinline__
void gemm_body(const __nv_bfloat16* __restrict__ Ahi, const __nv_bfloat16* __restrict__ Alo,
               const __nv_bfloat16* __restrict__ Bhi, const __nv_bfloat16* __restrict__ Blo,
               const float* __restrict__ bias, void* __restrict__ Cout,
               int Ntot, int m0, int n0, uint32_t sb)
{
    const int tid  = threadIdx.x;
    const int lane = tid & 31;
    const int wid  = tid >> 5;
    const int wm   = (wid & 1) * 64;
    const int wn   = (wid >> 1) * 64;
    const int gg   = lane >> 2, tg = lane & 3;
    const int mi   = lane >> 3;

    float acc[4][8][4];
    #pragma unroll
    for (int a = 0; a < 4; a++)
        #pragma unroll
        for (int b = 0; b < 8; b++)
            #pragma unroll
            for (int c = 0; c < 4; c++) acc[a][b][c] = 0.f;

    auto load_stage = [&](int it) {
        const uint32_t st = sb + (it % 3) * GSTAGE;
        const int k0 = it * 32;
        #pragma unroll
        for (int t = 0; t < 4; t++) {
            const int f   = tid + t * 128;
            const int row = f >> 2, c = f & 3;
            const uint32_t sw = row * 64 + ((c ^ ((row >> 1) & 3)) * 16);
            CP16(st + sw,         Ahi + (size_t)(m0 + row) * GK + k0 + c * 8);
            CP16(st + 8192 + sw,  Alo + (size_t)(m0 + row) * GK + k0 + c * 8);
            CP16(st + 16384 + sw, Bhi + (size_t)(n0 + row) * GK + k0 + c * 8);
            CP16(st + 24576 + sw, Blo + (size_t)(n0 + row) * GK + k0 + c * 8);
        }
    };

    load_stage(0); CPCOMMIT();
    load_stage(1); CPCOMMIT();

    const int NIT = GK / 32;
    for (int it = 0; it < NIT; it++) {
        if (it + 1 < NIT) { CPWAIT(1); } else { CPWAIT(0); }
        __syncthreads();
        const uint32_t st = sb + (it % 3) * GSTAGE;

        #pragma unroll
        for (int s = 0; s < 2; s++) {
            uint32_t aH[4][4], aL[4][4];
            #pragma unroll
            for (int mt = 0; mt < 4; mt++) {
                const int r = wm + mt * 16 + (mi & 1) * 8 + (lane & 7);
                const int c = 2 * s + (mi >> 1);
                const uint32_t ad = st + r * 64 + ((c ^ ((r >> 1) & 3)) * 16);
                ldsm_x4(aH[mt][0], aH[mt][1], aH[mt][2], aH[mt][3], ad);
                ldsm_x4(aL[mt][0], aL[mt][1], aL[mt][2], aL[mt][3], ad + 8192);
            }
            uint32_t bH[8][2], bL[8][2];
            #pragma unroll
            for (int nt = 0; nt < 4; nt++) {
                const int r = wn + nt * 16 + (mi >> 1) * 8 + (lane & 7);
                const int c = 2 * s + (mi & 1);
                const uint32_t bd = st + 16384 + r * 64 + ((c ^ ((r >> 1) & 3)) * 16);
                ldsm_x4(bH[2*nt][0], bH[2*nt][1], bH[2*nt+1][0], bH[2*nt+1][1], bd);
                ldsm_x4(bL[2*nt][0], bL[2*nt][1], bL[2*nt+1][0], bL[2*nt+1][1], bd + 8192);
            }
            #pragma unroll
            for (int mt = 0; mt < 4; mt++)
                #pragma unroll
                for (int n = 0; n < 8; n++) {
                    mma_bf16(acc[mt][n], aH[mt], bH[n][0], bH[n][1]);
                    mma_bf16(acc[mt][n], aH[mt], bL[n][0], bL[n][1]);
                    mma_bf16(acc[mt][n], aL[mt], bH[n][0], bH[n][1]);
                }
        }
        if (it + 2 < NIT) { load_stage(it + 2); CPCOMMIT(); }
    }

    #pragma unroll
    for (int mt = 0; mt < 4; mt++)
        #pragma unroll
        for (int n = 0; n < 8; n++) {
            const int r0  = m0 + wm + mt * 16 + gg;
            const int col = n0 + wn + n * 8 + tg * 2;
            const float b0 = bias[col], b1 = bias[col + 1];
            if (MODE == 0) {
                float* C = (float*)Cout;
                *(float2*)(C + (size_t)r0 * Ntot + col) =
                    make_float2(acc[mt][n][0] + b0, acc[mt][n][1] + b1);
                *(float2*)(C + (size_t)(r0 + 8) * Ntot + col) =
                    make_float2(acc[mt][n][2] + b0, acc[mt][n][3] + b1);
            } else {
                const float sc = (MODE == 2) ? QSCALE : 1.0f;
                __half* C = (__half*)Cout;
                __half2 h0 = __floats2half2_rn((acc[mt][n][0] + b0) * sc,
                                               (acc[mt][n][1] + b1) * sc);
                __half2 h1 = __floats2half2_rn((acc[mt][n][2] + b0) * sc,
                                               (acc[mt][n][3] + b1) * sc);
                *(__half2*)(C + (size_t)r0 * Ntot + col) = h0;
                *(__half2*)(C + (size_t)(r0 + 8) * Ntot + col) = h1;
            }
        }
}

__global__ __launch_bounds__(128, 2)
void gemm_qkv(const __nv_bfloat16* __restrict__ Qhi, const __nv_bfloat16* __restrict__ Qlo,
              const __nv_bfloat16* __restrict__ Khi, const __nv_bfloat16* __restrict__ Klo,
              const __nv_bfloat16* __restrict__ Vhi, const __nv_bfloat16* __restrict__ Vlo,
              const __nv_bfloat16* __restrict__ WQhi, const __nv_bfloat16* __restrict__ WQlo,
              const __nv_bfloat16* __restrict__ WKhi, const __nv_bfloat16* __restrict__ WKlo,
              const __nv_bfloat16* __restrict__ WVhi, const __nv_bfloat16* __restrict__ WVlo,
              const float* __restrict__ bq, const float* __restrict__ bk,
              const float* __restrict__ bv,
              __half* __restrict__ qh, __half* __restrict__ kh, __half* __restrict__ vh)
{
    extern __shared__ char sm[];
    const uint32_t sb = smem_u32(sm);
    const int bx = blockIdx.x;
    const int m0 = blockIdx.y * 128;
    if (bx < 16)
        gemm_body<2>(Qhi, Qlo, WQhi, WQlo, bq, qh, D_MODEL, m0, bx * 128, sb);
    else if (bx < 20)
        gemm_body<1>(Khi, Klo, WKhi, WKlo, bk, kh, KV_W, m0, (bx - 16) * 128, sb);
    else
        gemm_body<1>(Vhi, Vlo, WVhi, WVlo, bv, vh, KV_W, m0, (bx - 20) * 128, sb);
}

__global__ __launch_bounds__(128, 2)
void gemm_o(const __nv_bfloat16* __restrict__ Ahi, const __nv_bfloat16* __restrict__ Alo,
            const __nv_bfloat16* __restrict__ Bhi, const __nv_bfloat16* __restrict__ Blo,
            const float* __restrict__ bias, float* __restrict__ Cout)
{
    extern __shared__ char sm[];
    gemm_body<0>(Ahi, Alo, Bhi, Blo, bias, Cout, D_MODEL,
                 blockIdx.y * 128, blockIdx.x * 128, smem_u32(sm));
}

// ---------------------------------------------------------------------------
// fp16 HMMA causal flash attention.  q-tile 128/CTA, 8 warps (16 rows each),
// kv tile 64, double-buffered, 2 CTAs/SM.  Output bf16 hi/lo split.
// ---------------------------------------------------------------------------
__global__ __launch_bounds__(256, 2)
void flash(const __half* __restrict__ qbuf, const __half* __restrict__ kbuf,
           const __half* __restrict__ vbuf,
           __nv_bfloat16* __restrict__ ohi, __nv_bfloat16* __restrict__ olo)
{
    __shared__ __align__(16) __half sQ[128 * 64];
    __shared__ __align__(16) __half sK[2][64 * 64];
    __shared__ __align__(16) __half sV[2][64 * 64];

    const int qt   = (int)gridDim.x - 1 - (int)blockIdx.x;
    const int h    = blockIdx.y;
    const int g    = h >> 2;
    const int tid  = threadIdx.x;
    const int warp = tid >> 5, lane = tid & 31;
    const int gg   = lane >> 2, tg = lane & 3;
    const int mi   = lane >> 3;
    const int q0   = qt * 128;
    const int wrow = q0 + warp * 16;          // 8 warps x 16 rows

    const uint32_t qb  = smem_u32(sQ);
    const uint32_t kb0 = smem_u32(sK);
    const uint32_t vb0 = smem_u32(sV);

    // load Q tile: 128 rows x 8 segs = 1024 cp16 over 256 threads
    #pragma unroll
    for (int i = 0; i < 4; i++) {
        const int f = tid + i * 256;
        const int r = f >> 3, c = f & 7;
        CP16(qb + r * 128 + ((c ^ (r & 7)) * 16),
             qbuf + (size_t)(q0 + r) * D_MODEL + h * 64 + c * 8);
    }
    auto loadKV = [&](int kt) {
        const uint32_t ko = kb0 + (kt & 1) * 8192;
        const uint32_t vo = vb0 + (kt & 1) * 8192;
        #pragma unroll
        for (int i = 0; i < 2; i++) {
            const int f = tid + i * 256;
            const int r = f >> 3, c = f & 7;
            const size_t src = (size_t)(kt * 64 + r) * KV_W + g * 64 + c * 8;
            const uint32_t d = r * 128 + ((c ^ (r & 7)) * 16);
            CP16(ko + d, kbuf + src);
            CP16(vo + d, vbuf + src);
        }
    };
    loadKV(0);
    CPCOMMIT();
    CPWAIT(0);
    __syncthreads();

    // Q fragments (warp-resident): 16 rows x 64 cols = 4 k-steps
    uint32_t qa[4][4];
    {
        const int r = warp * 16 + (mi & 1) * 8 + (lane & 7);
        #pragma unroll
        for (int s = 0; s < 4; s++) {
            const int c = 2 * s + (mi >> 1);
            ldsm_x4(qa[s][0], qa[s][1], qa[s][2], qa[s][3],
                    qb + r * 128 + ((c ^ (r & 7)) * 16));
        }
    }

    float o[8][4];
    #pragma unroll
    for (int n = 0; n < 8; n++)
        #pragma unroll
        for (int c = 0; c < 4; c++) o[n][c] = 0.f;
    float m0v = -1e30f, m1v = -1e30f, l0 = 0.f, l1 = 0.f;
    const int r0g = wrow + gg;
    const int r1g = r0g + 8;

    const int KT = 2 * qt + 2;
    for (int kt = 0; kt < KT; kt++) {
        if (kt + 1 < KT) { loadKV(kt + 1); CPCOMMIT(); CPWAIT(1); }
        else             { CPWAIT(0); }
        __syncthreads();
        const uint32_t ko = kb0 + (kt & 1) * 8192;
        const uint32_t vo = vb0 + (kt & 1) * 8192;

        // ---- S = Q K^T ----
        float sc[8][4];
        #pragma unroll
        for (int n = 0; n < 8; n++)
            #pragma unroll
            for (int c = 0; c < 4; c++) sc[n][c] = 0.f;

        #pragma unroll
        for (int s = 0; s < 4; s++) {
            uint32_t bfr[8][2];
            #pragma unroll
            for (int nt = 0; nt < 4; nt++) {
                const int r = nt * 16 + (mi >> 1) * 8 + (lane & 7);
                const int c = 2 * s + (mi & 1);
                ldsm_x4(bfr[2*nt][0], bfr[2*nt][1], bfr[2*nt+1][0], bfr[2*nt+1][1],
                        ko + r * 128 + ((c ^ (r & 7)) * 16));
            }
            #pragma unroll
            for (int n = 0; n < 8; n++)
                mma_f16(sc[n], qa[s], bfr[n][0], bfr[n][1]);
        }

        // causal mask (only the tile overlapping this warp's rows)
        if (kt * 64 + 63 > r0g) {
            #pragma unroll
            for (int n = 0; n < 8; n++) {
                const int col = kt * 64 + n * 8 + tg * 2;
                if (col     > r0g) sc[n][0] = -1e30f;
                if (col + 1 > r0g) sc[n][1] = -1e30f;
                if (col     > r1g) sc[n][2] = -1e30f;
                if (col + 1 > r1g) sc[n][3] = -1e30f;
            }
        }

        // ---- online softmax (exp2 domain) ----
        float mx0 = -1e30f, mx1 = -1e30f;
        #pragma unroll
        for (int n = 0; n < 8; n++) {
            mx0 = fmaxf(mx0, fmaxf(sc[n][0], sc[n][1]));
            mx1 = fmaxf(mx1, fmaxf(sc[n][2], sc[n][3]));
        }
        mx0 = fmaxf(mx0, __shfl_xor_sync(0xffffffffu, mx0, 1));
        mx0 = fmaxf(mx0, __shfl_xor_sync(0xffffffffu, mx0, 2));
        mx1 = fmaxf(mx1, __shfl_xor_sync(0xffffffffu, mx1, 1));
        mx1 = fmaxf(mx1, __shfl_xor_sync(0xffffffffu, mx1, 2));
        const float mn0 = fmaxf(m0v, mx0), mn1 = fmaxf(m1v, mx1);
        const float c0 = exp2f(m0v - mn0), c1 = exp2f(m1v - mn1);
        m0v = mn0; m1v = mn1;

        float ps0 = 0.f, ps1 = 0.f;
        #pragma unroll
        for (int n = 0; n < 8; n++) {
            sc[n][0] = exp2f(sc[n][0] - mn0);
            sc[n][1] = exp2f(sc[n][1] - mn0);
            sc[n][2] = exp2f(sc[n][2] - mn1);
            sc[n][3] = exp2f(sc[n][3] - mn1);
            ps0 += sc[n][0] + sc[n][1];
            ps1 += sc[n][2] + sc[n][3];
        }
        l0 = l0 * c0 + ps0;
        l1 = l1 * c1 + ps1;
        #pragma unroll
        for (int n = 0; n < 8; n++) {
            o[n][0] *= c0; o[n][1] *= c0;
            o[n][2] *= c1; o[n][3] *= c1;
        }

        // P fragments (fp16)
        uint32_t pa[4][4];
        #pragma unroll
        for (int s = 0; s < 4; s++) {
            __half2 p0 = __floats2half2_rn(sc[2*s][0],   sc[2*s][1]);
            __half2 p1 = __floats2half2_rn(sc[2*s][2],   sc[2*s][3]);
            __half2 p2 = __floats2half2_rn(sc[2*s+1][0], sc[2*s+1][1]);
            __half2 p3 = __floats2half2_rn(sc[2*s+1][2], sc[2*s+1][3]);
            pa[s][0] = *(uint32_t*)&p0;
            pa[s][1] = *(uint32_t*)&p1;
            pa[s][2] = *(uint32_t*)&p2;
            pa[s][3] = *(uint32_t*)&p3;
        }

        // ---- O += P V ----
        #pragma unroll
        for (int s = 0; s < 4; s++) {
            uint32_t vfr[8][2];
            #pragma unroll
            for (int nt = 0; nt < 4; nt++) {
                const int r = s * 16 + (mi & 1) * 8 + (lane & 7);
                const int c = 2 * nt + (mi >> 1);
                ldsm_x4t(vfr[2*nt][0], vfr[2*nt][1], vfr[2*nt+1][0], vfr[2*nt+1][1],
                         vo + r * 128 + ((c ^ (r & 7)) * 16));
            }
            #pragma unroll
            for (int n = 0; n < 8; n++)
                mma_f16(o[n], pa[s], vfr[n][0], vfr[n][1]);
        }
        __syncthreads();
    }

    // finalize: normalize, split into bf16 hi/lo, store
    l0 += __shfl_xor_sync(0xffffffffu, l0, 1);
    l0 += __shfl_xor_sync(0xffffffffu, l0, 2);
    l1 += __shfl_xor_sync(0xffffffffu, l1, 1);
    l1 += __shfl_xor_sync(0xffffffffu, l1, 2);
    const float i0 = 1.f / l0, i1 = 1.f / l1;

    #pragma unroll
    for (int n = 0; n < 8; n++) {
        const int col = h * 64 + n * 8 + tg * 2;
        float v0 = o[n][0] * i0, v1 = o[n][1] * i0;
        float v2 = o[n][2] * i1, v3 = o[n][3] * i1;
        __nv_bfloat162 h0 = __floats2bfloat162_rn(v0, v1);
        __nv_bfloat162 h1 = __floats2bfloat162_rn(v2, v3);
        __nv_bfloat162 e0 = __floats2bfloat162_rn(v0 - __bfloat162float(h0.x),
                                                  v1 - __bfloat162float(h0.y));
        __nv_bfloat162 e1 = __floats2bfloat162_rn(v2 - __bfloat162float(h1.x),
                                                  v3 - __bfloat162float(h1.y));
        *(uint32_t*)(ohi + (size_t)r0g * D_MODEL + col) = *(uint32_t*)&h0;
        *(uint32_t*)(olo + (size_t)r0g * D_MODEL + col) = *(uint32_t*)&e0;
        *(uint32_t*)(ohi + (size_t)r1g * D_MODEL + col) = *(uint32_t*)&h1;
        *(uint32_t*)(olo + (size_t)r1g * D_MODEL + col) = *(uint32_t*)&e1;
    }
}

// ---------------------------------------------------------------------------
// Launch
// ---------------------------------------------------------------------------
extern "C" void kernel_launch(void* const* d_in, const int* in_sizes, int n_in,
                              void* d_out, int out_size)
{
    const float* queries = (const float*)d_in[0];
    const float* keys    = (const float*)d_in[1];
    const float* values  = (const float*)d_in[2];
    const float* Wq      = (const float*)d_in[3];
    const float* bq      = (const float*)d_in[4];
    const float* Wk      = (const float*)d_in[5];
    const float* bk      = (const float*)d_in[6];
    const float* Wv      = (const float*)d_in[7];
    const float* bv      = (const float*)d_in[8];
    const float* Wo      = (const float*)d_in[9];
    const float* bo      = (const float*)d_in[10];
    float*       out     = (float*)d_out;

    __half *qh, *kh, *vh;
    __nv_bfloat16 *ahi, *alo, *bhi, *blo, *chi, *clo;
    __nv_bfloat16 *wqh, *wql, *wkh, *wkl, *wvh, *wvl, *woh, *wol;
    cudaGetSymbolAddress((void**)&qh,  g_qh);
    cudaGetSymbolAddress((void**)&kh,  g_kh);
    cudaGetSymbolAddress((void**)&vh,  g_vh);
    cudaGetSymbolAddress((void**)&ahi, g_ahi);
    cudaGetSymbolAddress((void**)&alo, g_alo);
    cudaGetSymbolAddress((void**)&bhi, g_bhi);
    cudaGetSymbolAddress((void**)&blo, g_blo);
    cudaGetSymbolAddress((void**)&chi, g_chi);
    cudaGetSymbolAddress((void**)&clo, g_clo);
    cudaGetSymbolAddress((void**)&wqh, g_wq_hi);
    cudaGetSymbolAddress((void**)&wql, g_wq_lo);
    cudaGetSymbolAddress((void**)&wkh, g_wk_hi);
    cudaGetSymbolAddress((void**)&wkl, g_wk_lo);
    cudaGetSymbolAddress((void**)&wvh, g_wv_hi);
    cudaGetSymbolAddress((void**)&wvl, g_wv_lo);
    cudaGetSymbolAddress((void**)&woh, g_wo_hi);
    cudaGetSymbolAddress((void**)&wol, g_wo_lo);

    cudaFuncSetAttribute(gemm_qkv, cudaFuncAttributeMaxDynamicSharedMemorySize, 3 * GSTAGE);
    cudaFuncSetAttribute(gemm_o,   cudaFuncAttributeMaxDynamicSharedMemorySize, 3 * GSTAGE);

    const int NELEM4 = S_LEN * D_MODEL / 4;

    // weight prep
    wsplit4<<<dim3(D_MODEL / 32, GK / 32, 4), 256>>>(
        Wq, Wk, Wv, Wo, wqh, wql, wkh, wkl, wvh, wvl, woh, wol);

    // activation splits
    asplit3<<<dim3(NELEM4 / 256, 3), 256>>>(
        (const float4*)queries, (const float4*)keys, (const float4*)values,
        ahi, alo, bhi, blo, chi, clo);

    // Q + K + V projections fused
    gemm_qkv<<<dim3(24, S_LEN / 128), 128, 3 * GSTAGE>>>(
        ahi, alo, bhi, blo, chi, clo,
        wqh, wql, wkh, wkl, wvh, wvl,
        bq, bk, bv, qh, kh, vh);

    // causal GQA flash attention -> bf16 hi/lo split output
    flash<<<dim3(S_LEN / 128, H_Q), 256>>>(qh, kh, vh, ahi, alo);

    // output projection
    gemm_o<<<dim3(D_MODEL / 128, S_LEN / 128), 128, 3 * GSTAGE>>>(
        ahi, alo, woh, wol, bo, out);
}

// round 8
// speedup vs baseline: 1.0325x; 1.0325x over previous
#include <cuda_runtime.h>
#include <cuda_bf16.h>
#include <cuda_fp16.h>
#include <cstdint>

// ===========================================================================
// GQA layer, sm_103 baseline-PTX path: mma.sync (HMMA) everywhere.
//   - projections: bf16 split-2 GEMM, CTA tile 128x128 (4 warps, 64x64 each),
//       3-stage cp.async, 2 CTAs/SM, Q+K+V fused into one launch
//   - attention:   fp16 FA-2, q-tile 128/CTA, 4 warps (32 rows each),
//       ex2.approx.f16x2 softmax + MMA row-sums, bf16-split output
// ===========================================================================

#define S_LEN   2048
#define D_MODEL 2048
#define H_Q     32
#define KV_W    512
#define GK      2048
#define QSCALE  0.1803368801111244f   // 0.125 * log2(e)
#define ONES2   0x3C003C00u           // half2(1.0, 1.0)

// ------------------------------ scratch ------------------------------------
__device__ __align__(16) __half g_qh[S_LEN * D_MODEL];
__device__ __align__(16) __half g_kh[S_LEN * KV_W];
__device__ __align__(16) __half g_vh[S_LEN * KV_W];

__device__ __align__(16) __nv_bfloat16 g_ahi[S_LEN * D_MODEL];
__device__ __align__(16) __nv_bfloat16 g_alo[S_LEN * D_MODEL];
__device__ __align__(16) __nv_bfloat16 g_bhi[S_LEN * D_MODEL];
__device__ __align__(16) __nv_bfloat16 g_blo[S_LEN * D_MODEL];
__device__ __align__(16) __nv_bfloat16 g_chi[S_LEN * D_MODEL];
__device__ __align__(16) __nv_bfloat16 g_clo[S_LEN * D_MODEL];

__device__ __align__(16) __nv_bfloat16 g_wq_hi[D_MODEL * GK];
__device__ __align__(16) __nv_bfloat16 g_wq_lo[D_MODEL * GK];
__device__ __align__(16) __nv_bfloat16 g_wk_hi[KV_W * GK];
__device__ __align__(16) __nv_bfloat16 g_wk_lo[KV_W * GK];
__device__ __align__(16) __nv_bfloat16 g_wv_hi[KV_W * GK];
__device__ __align__(16) __nv_bfloat16 g_wv_lo[KV_W * GK];
__device__ __align__(16) __nv_bfloat16 g_wo_hi[D_MODEL * GK];
__device__ __align__(16) __nv_bfloat16 g_wo_lo[D_MODEL * GK];

// ------------------------------ helpers ------------------------------------
__device__ __forceinline__ uint32_t smem_u32(const void* p) {
    uint32_t a;
    asm("{ .reg .u64 t; cvta.to.shared.u64 t, %1; cvt.u32.u64 %0, t; }"
        : "=r"(a) : "l"(p));
    return a;
}

#define CP16(dst, src) \
    asm volatile("cp.async.cg.shared.global [%0], [%1], 16;" \
                 :: "r"(dst), "l"(src))
#define CPCOMMIT() asm volatile("cp.async.commit_group;" ::: "memory")
#define CPWAIT(n)  asm volatile("cp.async.wait_group %0;" :: "n"(n) : "memory")

__device__ __forceinline__ void ldsm_x4(uint32_t& r0, uint32_t& r1,
                                        uint32_t& r2, uint32_t& r3, uint32_t a) {
    asm volatile("ldmatrix.sync.aligned.m8n8.x4.shared.b16 {%0,%1,%2,%3}, [%4];"
                 : "=r"(r0), "=r"(r1), "=r"(r2), "=r"(r3) : "r"(a));
}
__device__ __forceinline__ void ldsm_x4t(uint32_t& r0, uint32_t& r1,
                                         uint32_t& r2, uint32_t& r3, uint32_t a) {
    asm volatile("ldmatrix.sync.aligned.m8n8.x4.trans.shared.b16 {%0,%1,%2,%3}, [%4];"
                 : "=r"(r0), "=r"(r1), "=r"(r2), "=r"(r3) : "r"(a));
}

__device__ __forceinline__ void mma_bf16(float* c, const uint32_t* a,
                                         uint32_t b0, uint32_t b1) {
    asm volatile("mma.sync.aligned.m16n8k16.row.col.f32.bf16.bf16.f32 "
                 "{%0,%1,%2,%3}, {%4,%5,%6,%7}, {%8,%9}, {%0,%1,%2,%3};"
                 : "+f"(c[0]), "+f"(c[1]), "+f"(c[2]), "+f"(c[3])
                 : "r"(a[0]), "r"(a[1]), "r"(a[2]), "r"(a[3]), "r"(b0), "r"(b1));
}
__device__ __forceinline__ void mma_f16(float* c, const uint32_t* a,
                                        uint32_t b0, uint32_t b1) {
    asm volatile("mma.sync.aligned.m16n8k16.row.col.f32.f16.f16.f32 "
                 "{%0,%1,%2,%3}, {%4,%5,%6,%7}, {%8,%9}, {%0,%1,%2,%3};"
                 : "+f"(c[0]), "+f"(c[1]), "+f"(c[2]), "+f"(c[3])
                 : "r"(a[0]), "r"(a[1]), "r"(a[2]), "r"(a[3]), "r"(b0), "r"(b1));
}

__device__ __forceinline__ uint32_t h2exp2(uint32_t x) {
    uint32_t r;
    asm("ex2.approx.f16x2 %0, %1;" : "=r"(r) : "r"(x));
    return r;
}
__device__ __forceinline__ uint32_t packh2(float a, float b) {
    __half2 h = __floats2half2_rn(a, b);
    return *reinterpret_cast<uint32_t*>(&h);
}

// ---------------------------------------------------------------------------
// asplit3
// ---------------------------------------------------------------------------
__global__ __launch_bounds__(256)
void asplit3(const float4* __restrict__ Q, const float4* __restrict__ K,
             const float4* __restrict__ V,
             __nv_bfloat16* __restrict__ ahi, __nv_bfloat16* __restrict__ alo,
             __nv_bfloat16* __restrict__ bhi, __nv_bfloat16* __restrict__ blo,
             __nv_bfloat16* __restrict__ chi, __nv_bfloat16* __restrict__ clo)
{
    const int z = blockIdx.y;
    const float4* A;  __nv_bfloat16 *hi, *lo;
    if      (z == 0) { A = Q; hi = ahi; lo = alo; }
    else if (z == 1) { A = K; hi = bhi; lo = blo; }
    else             { A = V; hi = chi; lo = clo; }

    const int i = blockIdx.x * 256 + threadIdx.x;
    float4 v = A[i];
    __nv_bfloat162 h0 = __floats2bfloat162_rn(v.x, v.y);
    __nv_bfloat162 h1 = __floats2bfloat162_rn(v.z, v.w);
    __nv_bfloat162 l0 = __floats2bfloat162_rn(v.x - __bfloat162float(h0.x),
                                              v.y - __bfloat162float(h0.y));
    __nv_bfloat162 l1 = __floats2bfloat162_rn(v.z - __bfloat162float(h1.x),
                                              v.w - __bfloat162float(h1.y));
    uint2 uh = make_uint2(*(uint32_t*)&h0, *(uint32_t*)&h1);
    uint2 ul = make_uint2(*(uint32_t*)&l0, *(uint32_t*)&l1);
    *(uint2*)(hi + (size_t)i * 4) = uh;
    *(uint2*)(lo + (size_t)i * 4) = ul;
}

// ---------------------------------------------------------------------------
// wsplit4
// ---------------------------------------------------------------------------
__global__ __launch_bounds__(256)
void wsplit4(const float* __restrict__ Wq, const float* __restrict__ Wk,
             const float* __restrict__ Wv, const float* __restrict__ Wo,
             __nv_bfloat16* __restrict__ qhi, __nv_bfloat16* __restrict__ qlo,
             __nv_bfloat16* __restrict__ khi, __nv_bfloat16* __restrict__ klo,
             __nv_bfloat16* __restrict__ vhi, __nv_bfloat16* __restrict__ vlo,
             __nv_bfloat16* __restrict__ ohi, __nv_bfloat16* __restrict__ olo)
{
    __shared__ float tile[32][33];
    const int z = blockIdx.z;
    const float* W;  __nv_bfloat16 *hi, *lo;  int Ncols;
    if      (z == 0) { W = Wq; hi = qhi; lo = qlo; Ncols = D_MODEL; }
    else if (z == 1) { W = Wk; hi = khi; lo = klo; Ncols = KV_W; }
    else if (z == 2) { W = Wv; hi = vhi; lo = vlo; Ncols = KV_W; }
    else             { W = Wo; hi = ohi; lo = olo; Ncols = D_MODEL; }

    const int bx = blockIdx.x, by = blockIdx.y;
    if (bx * 32 >= Ncols) return;
    const int tx = threadIdx.x & 31, ty = threadIdx.x >> 5;

    #pragma unroll
    for (int i = 0; i < 32; i += 8)
        tile[ty + i][tx] = W[(size_t)(by * 32 + ty + i) * Ncols + bx * 32 + tx];
    __syncthreads();
    #pragma unroll
    for (int i = 0; i < 32; i += 8) {
        const int n = bx * 32 + ty + i;
        const int k = by * 32 + tx;
        float x = tile[tx][ty + i];
        __nv_bfloat16 h = __float2bfloat16_rn(x);
        hi[(size_t)n * GK + k] = h;
        lo[(size_t)n * GK + k] = __float2bfloat16_rn(x - __bfloat162float(h));
    }
}

// ---------------------------------------------------------------------------
// GEMM body: 128x128 tile, 4 warps, 3-stage, 2 CTA/SM
// ---------------------------------------------------------------------------
#define GSTAGE 32768

template <int MODE>
__device__ __forceinline__
void gemm_body(const __nv_bfloat16* __restrict__ Ahi, const __nv_bfloat16* __restrict__ Alo,
               const __nv_bfloat16* __restrict__ Bhi, const __nv_bfloat16* __restrict__ Blo,
               const float* __restrict__ bias, void* __restrict__ Cout,
               int Ntot, int m0, int n0, uint32_t sb)
{
    const int tid  = threadIdx.x;
    const int lane = tid & 31;
    const int wid  = tid >> 5;
    const int wm   = (wid & 1) * 64;
    const int wn   = (wid >> 1) * 64;
    const int gg   = lane >> 2, tg = lane & 3;
    const int mi   = lane >> 3;

    float acc[4][8][4];
    #pragma unroll
    for (int a = 0; a < 4; a++)
        #pragma unroll
        for (int b = 0; b < 8; b++)
            #pragma unroll
            for (int c = 0; c < 4; c++) acc[a][b][c] = 0.f;

    auto load_stage = [&](int it) {
        const uint32_t st = sb + (it % 3) * GSTAGE;
        const int k0 = it * 32;
        #pragma unroll
        for (int t = 0; t < 4; t++) {
            const int f   = tid + t * 128;
            const int row = f >> 2, c = f & 3;
            const uint32_t sw = row * 64 + ((c ^ ((row >> 1) & 3)) * 16);
            CP16(st + sw,         Ahi + (size_t)(m0 + row) * GK + k0 + c * 8);
            CP16(st + 8192 + sw,  Alo + (size_t)(m0 + row) * GK + k0 + c * 8);
            CP16(st + 16384 + sw, Bhi + (size_t)(n0 + row) * GK + k0 + c * 8);
            CP16(st + 24576 + sw, Blo + (size_t)(n0 + row) * GK + k0 + c * 8);
        }
    };

    load_stage(0); CPCOMMIT();
    load_stage(1); CPCOMMIT();

    const int NIT = GK / 32;
    for (int it = 0; it < NIT; it++) {
        if (it + 1 < NIT) { CPWAIT(1); } else { CPWAIT(0); }
        __syncthreads();
        const uint32_t st = sb + (it % 3) * GSTAGE;

        #pragma unroll
        for (int s = 0; s < 2; s++) {
            uint32_t aH[4][4], aL[4][4];
            #pragma unroll
            for (int mt = 0; mt < 4; mt++) {
                const int r = wm + mt * 16 + (mi & 1) * 8 + (lane & 7);
                const int c = 2 * s + (mi >> 1);
                const uint32_t ad = st + r * 64 + ((c ^ ((r >> 1) & 3)) * 16);
                ldsm_x4(aH[mt][0], aH[mt][1], aH[mt][2], aH[mt][3], ad);
                ldsm_x4(aL[mt][0], aL[mt][1], aL[mt][2], aL[mt][3], ad + 8192);
            }
            uint32_t bH[8][2], bL[8][2];
            #pragma unroll
            for (int nt = 0; nt < 4; nt++) {
                const int r = wn + nt * 16 + (mi >> 1) * 8 + (lane & 7);
                const int c = 2 * s + (mi & 1);
                const uint32_t bd = st + 16384 + r * 64 + ((c ^ ((r >> 1) & 3)) * 16);
                ldsm_x4(bH[2*nt][0], bH[2*nt][1], bH[2*nt+1][0], bH[2*nt+1][1], bd);
                ldsm_x4(bL[2*nt][0], bL[2*nt][1], bL[2*nt+1][0], bL[2*nt+1][1], bd + 8192);
            }
            #pragma unroll
            for (int mt = 0; mt < 4; mt++)
                #pragma unroll
                for (int n = 0; n < 8; n++) {
                    mma_bf16(acc[mt][n], aH[mt], bH[n][0], bH[n][1]);
                    mma_bf16(acc[mt][n], aH[mt], bL[n][0], bL[n][1]);
                    mma_bf16(acc[mt][n], aL[mt], bH[n][0], bH[n][1]);
                }
        }
        if (it + 2 < NIT) { load_stage(it + 2); CPCOMMIT(); }
    }

    #pragma unroll
    for (int mt = 0; mt < 4; mt++)
        #pragma unroll
        for (int n = 0; n < 8; n++) {
            const int r0  = m0 + wm + mt * 16 + gg;
            const int col = n0 + wn + n * 8 + tg * 2;
            const float b0 = bias[col], b1 = bias[col + 1];
            if (MODE == 0) {
                float* C = (float*)Cout;
                *(float2*)(C + (size_t)r0 * Ntot + col) =
                    make_float2(acc[mt][n][0] + b0, acc[mt][n][1] + b1);
                *(float2*)(C + (size_t)(r0 + 8) * Ntot + col) =
                    make_float2(acc[mt][n][2] + b0, acc[mt][n][3] + b1);
            } else {
                const float sc = (MODE == 2) ? QSCALE : 1.0f;
                __half* C = (__half*)Cout;
                __half2 h0 = __floats2half2_rn((acc[mt][n][0] + b0) * sc,
                                               (acc[mt][n][1] + b1) * sc);
                __half2 h1 = __floats2half2_rn((acc[mt][n][2] + b0) * sc,
                                               (acc[mt][n][3] + b1) * sc);
                *(__half2*)(C + (size_t)r0 * Ntot + col) = h0;
                *(__half2*)(C + (size_t)(r0 + 8) * Ntot + col) = h1;
            }
        }
}

__global__ __launch_bounds__(128, 2)
void gemm_qkv(const __nv_bfloat16* __restrict__ Qhi, const __nv_bfloat16* __restrict__ Qlo,
              const __nv_bfloat16* __restrict__ Khi, const __nv_bfloat16* __restrict__ Klo,
              const __nv_bfloat16* __restrict__ Vhi, const __nv_bfloat16* __restrict__ Vlo,
              const __nv_bfloat16* __restrict__ WQhi, const __nv_bfloat16* __restrict__ WQlo,
              const __nv_bfloat16* __restrict__ WKhi, const __nv_bfloat16* __restrict__ WKlo,
              const __nv_bfloat16* __restrict__ WVhi, const __nv_bfloat16* __restrict__ WVlo,
              const float* __restrict__ bq, const float* __restrict__ bk,
              const float* __restrict__ bv,
              __half* __restrict__ qh, __half* __restrict__ kh, __half* __restrict__ vh)
{
    extern __shared__ char sm[];
    const uint32_t sb = smem_u32(sm);
    const int bx = blockIdx.x;
    const int m0 = blockIdx.y * 128;
    if (bx < 16)
        gemm_body<2>(Qhi, Qlo, WQhi, WQlo, bq, qh, D_MODEL, m0, bx * 128, sb);
    else if (bx < 20)
        gemm_body<1>(Khi, Klo, WKhi, WKlo, bk, kh, KV_W, m0, (bx - 16) * 128, sb);
    else
        gemm_body<1>(Vhi, Vlo, WVhi, WVlo, bv, vh, KV_W, m0, (bx - 20) * 128, sb);
}

__global__ __launch_bounds__(128, 2)
void gemm_o(const __nv_bfloat16* __restrict__ Ahi, const __nv_bfloat16* __restrict__ Alo,
            const __nv_bfloat16* __restrict__ Bhi, const __nv_bfloat16* __restrict__ Blo,
            const float* __restrict__ bias, float* __restrict__ Cout)
{
    extern __shared__ char sm[];
    gemm_body<0>(Ahi, Alo, Bhi, Blo, bias, Cout, D_MODEL,
                 blockIdx.y * 128, blockIdx.x * 128, smem_u32(sm));
}

// ---------------------------------------------------------------------------
// fp16 HMMA causal flash attention.  q-tile 128/CTA, 4 warps (32 q-rows each),
// kv tile 64, double-buffered.  ex2.approx.f16x2 softmax, MMA row-sums.
// Output written as bf16 hi/lo split.
// ---------------------------------------------------------------------------
__global__ __launch_bounds__(128)
void flash(const __half* __restrict__ qbuf, const __half* __restrict__ kbuf,
           const __half* __restrict__ vbuf,
           __nv_bfloat16* __restrict__ ohi, __nv_bfloat16* __restrict__ olo)
{
    __shared__ __align__(16) __half sQ[128 * 64];
    __shared__ __align__(16) __half sK[2][64 * 64];
    __shared__ __align__(16) __half sV[2][64 * 64];

    const int qt   = (int)gridDim.x - 1 - (int)blockIdx.x;
    const int h    = blockIdx.y;
    const int g    = h >> 2;
    const int tid  = threadIdx.x;
    const int warp = tid >> 5, lane = tid & 31;
    const int gg   = lane >> 2, tg = lane & 3;
    const int mi   = lane >> 3;
    const int q0   = qt * 128;
    const int wrow = q0 + warp * 32;

    const uint32_t qb  = smem_u32(sQ);
    const uint32_t kb0 = smem_u32(sK);
    const uint32_t vb0 = smem_u32(sV);

    #pragma unroll
    for (int i = 0; i < 8; i++) {
        const int f = tid + i * 128;
        const int r = f >> 3, c = f & 7;
        CP16(qb + r * 128 + ((c ^ (r & 7)) * 16),
             qbuf + (size_t)(q0 + r) * D_MODEL + h * 64 + c * 8);
    }
    auto loadKV = [&](int kt) {
        const uint32_t ko = kb0 + (kt & 1) * 8192;
        const uint32_t vo = vb0 + (kt & 1) * 8192;
        #pragma unroll
        for (int i = 0; i < 4; i++) {
            const int f = tid + i * 128;
            const int r = f >> 3, c = f & 7;
            const size_t src = (size_t)(kt * 64 + r) * KV_W + g * 64 + c * 8;
            const uint32_t d = r * 128 + ((c ^ (r & 7)) * 16);
            CP16(ko + d, kbuf + src);
            CP16(vo + d, vbuf + src);
        }
    };
    loadKV(0);
    CPCOMMIT();
    CPWAIT(0);
    __syncthreads();

    uint32_t qa[4][2][4];
    #pragma unroll
    for (int mt = 0; mt < 2; mt++) {
        const int r = warp * 32 + mt * 16 + (mi & 1) * 8 + (lane & 7);
        #pragma unroll
        for (int s = 0; s < 4; s++) {
            const int c = 2 * s + (mi >> 1);
            ldsm_x4(qa[s][mt][0], qa[s][mt][1], qa[s][mt][2], qa[s][mt][3],
                    qb + r * 128 + ((c ^ (r & 7)) * 16));
        }
    }

    float o[2][8][4];
    #pragma unroll
    for (int mt = 0; mt < 2; mt++)
        #pragma unroll
        for (int n = 0; n < 8; n++)
            #pragma unroll
            for (int c = 0; c < 4; c++) o[mt][n][c] = 0.f;
    float mM[2][2] = {{-1e30f, -1e30f}, {-1e30f, -1e30f}};
    float lL[2][2] = {{0.f, 0.f}, {0.f, 0.f}};

    const int KT = 2 * qt + 2;
    for (int kt = 0; kt < KT; kt++) {
        if (kt + 1 < KT) { loadKV(kt + 1); CPCOMMIT(); CPWAIT(1); }
        else             { CPWAIT(0); }
        __syncthreads();
        const uint32_t ko = kb0 + (kt & 1) * 8192;
        const uint32_t vo = vb0 + (kt & 1) * 8192;

        // ---- S = Q K^T ----
        float sc[2][8][4];
        #pragma unroll
        for (int mt = 0; mt < 2; mt++)
            #pragma unroll
            for (int n = 0; n < 8; n++)
                #pragma unroll
                for (int c = 0; c < 4; c++) sc[mt][n][c] = 0.f;

        #pragma unroll
        for (int s = 0; s < 4; s++) {
            uint32_t bfr[8][2];
            #pragma unroll
            for (int nt = 0; nt < 4; nt++) {
                const int r = nt * 16 + (mi >> 1) * 8 + (lane & 7);
                const int c = 2 * s + (mi & 1);
                ldsm_x4(bfr[2*nt][0], bfr[2*nt][1], bfr[2*nt+1][0], bfr[2*nt+1][1],
                        ko + r * 128 + ((c ^ (r & 7)) * 16));
            }
            #pragma unroll
            for (int mt = 0; mt < 2; mt++)
                #pragma unroll
                for (int n = 0; n < 8; n++)
                    mma_f16(sc[mt][n], qa[s][mt], bfr[n][0], bfr[n][1]);
        }

        // causal mask
        if (kt * 64 + 63 > wrow) {
            #pragma unroll
            for (int mt = 0; mt < 2; mt++) {
                const int r0 = wrow + mt * 16 + gg;
                const int r1 = r0 + 8;
                #pragma unroll
                for (int n = 0; n < 8; n++) {
                    const int col = kt * 64 + n * 8 + tg * 2;
                    if (col     > r0) sc[mt][n][0] = -1e30f;
                    if (col + 1 > r0) sc[mt][n][1] = -1e30f;
                    if (col     > r1) sc[mt][n][2] = -1e30f;
                    if (col + 1 > r1) sc[mt][n][3] = -1e30f;
                }
            }
        }

        // ---- online softmax: P = ex2.approx.f16x2(sc - mn), l via MMA ----
        uint32_t pa[2][4][4];
        #pragma unroll
        for (int mt = 0; mt < 2; mt++) {
            float mx0 = -1e30f, mx1 = -1e30f;
            #pragma unroll
            for (int n = 0; n < 8; n++) {
                mx0 = fmaxf(mx0, fmaxf(sc[mt][n][0], sc[mt][n][1]));
                mx1 = fmaxf(mx1, fmaxf(sc[mt][n][2], sc[mt][n][3]));
            }
            mx0 = fmaxf(mx0, __shfl_xor_sync(0xffffffffu, mx0, 1));
            mx0 = fmaxf(mx0, __shfl_xor_sync(0xffffffffu, mx0, 2));
            mx1 = fmaxf(mx1, __shfl_xor_sync(0xffffffffu, mx1, 1));
            mx1 = fmaxf(mx1, __shfl_xor_sync(0xffffffffu, mx1, 2));
            const float mn0 = fmaxf(mM[mt][0], mx0);
            const float mn1 = fmaxf(mM[mt][1], mx1);
            const float c0 = exp2f(mM[mt][0] - mn0);
            const float c1 = exp2f(mM[mt][1] - mn1);
            mM[mt][0] = mn0; mM[mt][1] = mn1;

            // P fragments directly in fp16 (packed ex2)
            #pragma unroll
            for (int s = 0; s < 4; s++) {
                pa[mt][s][0] = h2exp2(packh2(sc[mt][2*s][0]   - mn0, sc[mt][2*s][1]   - mn0));
                pa[mt][s][1] = h2exp2(packh2(sc[mt][2*s][2]   - mn1, sc[mt][2*s][3]   - mn1));
                pa[mt][s][2] = h2exp2(packh2(sc[mt][2*s+1][0] - mn0, sc[mt][2*s+1][1] - mn0));
                pa[mt][s][3] = h2exp2(packh2(sc[mt][2*s+1][2] - mn1, sc[mt][2*s+1][3] - mn1));
            }

            // row sums via MMA with ones (exact fp32 accumulation of fp16 P)
            float lacc[4] = {0.f, 0.f, 0.f, 0.f};
            #pragma unroll
            for (int s = 0; s < 4; s++)
                mma_f16(lacc, pa[mt][s], ONES2, ONES2);
            lL[mt][0] = lL[mt][0] * c0 + lacc[0];
            lL[mt][1] = lL[mt][1] * c1 + lacc[2];

            #pragma unroll
            for (int n = 0; n < 8; n++) {
                o[mt][n][0] *= c0; o[mt][n][1] *= c0;
                o[mt][n][2] *= c1; o[mt][n][3] *= c1;
            }
        }

        // ---- O += P V ----
        #pragma unroll
        for (int s = 0; s < 4; s++) {
            uint32_t vfr[8][2];
            #pragma unroll
            for (int nt = 0; nt < 4; nt++) {
                const int r = s * 16 + (mi & 1) * 8 + (lane & 7);
                const int c = 2 * nt + (mi >> 1);
                ldsm_x4t(vfr[2*nt][0], vfr[2*nt][1], vfr[2*nt+1][0], vfr[2*nt+1][1],
                         vo + r * 128 + ((c ^ (r & 7)) * 16));
            }
            #pragma unroll
            for (int mt = 0; mt < 2; mt++)
                #pragma unroll
                for (int n = 0; n < 8; n++)
                    mma_f16(o[mt][n], pa[mt][s], vfr[n][0], vfr[n][1]);
        }
        __syncthreads();
    }

    // finalize: normalize (lL already holds full row sums), split bf16, store
    #pragma unroll
    for (int mt = 0; mt < 2; mt++) {
        const float i0 = 1.f / lL[mt][0], i1 = 1.f / lL[mt][1];
        const int r0 = wrow + mt * 16 + gg;
        const int r1 = r0 + 8;
        #pragma unroll
        for (int n = 0; n < 8; n++) {
            const int col = h * 64 + n * 8 + tg * 2;
            float v0 = o[mt][n][0] * i0, v1 = o[mt][n][1] * i0;
            float v2 = o[mt][n][2] * i1, v3 = o[mt][n][3] * i1;
            __nv_bfloat162 h0 = __floats2bfloat162_rn(v0, v1);
            __nv_bfloat162 h1 = __floats2bfloat162_rn(v2, v3);
            __nv_bfloat162 e0 = __floats2bfloat162_rn(v0 - __bfloat162float(h0.x),
                                                      v1 - __bfloat162float(h0.y));
            __nv_bfloat162 e1 = __floats2bfloat162_rn(v2 - __bfloat162float(h1.x),
                                                      v3 - __bfloat162float(h1.y));
            *(uint32_t*)(ohi + (size_t)r0 * D_MODEL + col) = *(uint32_t*)&h0;
            *(uint32_t*)(olo + (size_t)r0 * D_MODEL + col) = *(uint32_t*)&e0;
            *(uint32_t*)(ohi + (size_t)r1 * D_MODEL + col) = *(uint32_t*)&h1;
            *(uint32_t*)(olo + (size_t)r1 * D_MODEL + col) = *(uint32_t*)&e1;
        }
    }
}

// ---------------------------------------------------------------------------
// Launch
// ---------------------------------------------------------------------------
extern "C" void kernel_launch(void* const* d_in, const int* in_sizes, int n_in,
                              void* d_out, int out_size)
{
    const float* queries = (const float*)d_in[0];
    const float* keys    = (const float*)d_in[1];
    const float* values  = (const float*)d_in[2];
    const float* Wq      = (const float*)d_in[3];
    const float* bq      = (const float*)d_in[4];
    const float* Wk      = (const float*)d_in[5];
    const float* bk      = (const float*)d_in[6];
    const float* Wv      = (const float*)d_in[7];
    const float* bv      = (const float*)d_in[8];
    const float* Wo      = (const float*)d_in[9];
    const float* bo      = (const float*)d_in[10];
    float*       out     = (float*)d_out;

    __half *qh, *kh, *vh;
    __nv_bfloat16 *ahi, *alo, *bhi, *blo, *chi, *clo;
    __nv_bfloat16 *wqh, *wql, *wkh, *wkl, *wvh, *wvl, *woh, *wol;
    cudaGetSymbolAddress((void**)&qh,  g_qh);
    cudaGetSymbolAddress((void**)&kh,  g_kh);
    cudaGetSymbolAddress((void**)&vh,  g_vh);
    cudaGetSymbolAddress((void**)&ahi, g_ahi);
    cudaGetSymbolAddress((void**)&alo, g_alo);
    cudaGetSymbolAddress((void**)&bhi, g_bhi);
    cudaGetSymbolAddress((void**)&blo, g_blo);
    cudaGetSymbolAddress((void**)&chi, g_chi);
    cudaGetSymbolAddress((void**)&clo, g_clo);
    cudaGetSymbolAddress((void**)&wqh, g_wq_hi);
    cudaGetSymbolAddress((void**)&wql, g_wq_lo);
    cudaGetSymbolAddress((void**)&wkh, g_wk_hi);
    cudaGetSymbolAddress((void**)&wkl, g_wk_lo);
    cudaGetSymbolAddress((void**)&wvh, g_wv_hi);
    cudaGetSymbolAddress((void**)&wvl, g_wv_lo);
    cudaGetSymbolAddress((void**)&woh, g_wo_hi);
    cudaGetSymbolAddress((void**)&wol, g_wo_lo);

    cudaFuncSetAttribute(gemm_qkv, cudaFuncAttributeMaxDynamicSharedMemorySize, 3 * GSTAGE);
    cudaFuncSetAttribute(gemm_o,   cudaFuncAttributeMaxDynamicSharedMemorySize, 3 * GSTAGE);

    const int NELEM4 = S_LEN * D_MODEL / 4;

    // weight prep
    wsplit4<<<dim3(D_MODEL / 32, GK / 32, 4), 256>>>(
        Wq, Wk, Wv, Wo, wqh, wql, wkh, wkl, wvh, wvl, woh, wol);

    // activation splits
    asplit3<<<dim3(NELEM4 / 256, 3), 256>>>(
        (const float4*)queries, (const float4*)keys, (const float4*)values,
        ahi, alo, bhi, blo, chi, clo);

    // Q + K + V projections fused
    gemm_qkv<<<dim3(24, S_LEN / 128), 128, 3 * GSTAGE>>>(
        ahi, alo, bhi, blo, chi, clo,
        wqh, wql, wkh, wkl, wvh, wvl,
        bq, bk, bv, qh, kh, vh);

    // causal GQA flash attention -> bf16 hi/lo split output
    flash<<<dim3(S_LEN / 128, H_Q), 128>>>(qh, kh, vh, ahi, alo);

    // output projection
    gemm_o<<<dim3(D_MODEL / 128, S_LEN / 128), 128, 3 * GSTAGE>>>(
        ahi, alo, woh, wol, bo, out);
}

// round 9
// speedup vs baseline: 1.0381x; 1.0054x over previous
#include <cuda_runtime.h>
#include <cuda_bf16.h>
#include <cuda_fp16.h>
#include <cstdint>

// ===========================================================================
// GQA layer, sm_103 baseline-PTX path: mma.sync (HMMA) everywhere.
//   - projections: bf16 split-2 GEMM, CTA tile 128x128 (4 warps, 64x64 each),
//       3-stage cp.async, 2 CTAs/SM, Q+K+V fused into one launch
//   - attention:   fp16 FA-2, q-tile 128/CTA, 4 warps, 3-stage KV ring,
//       1 sync/iter, ex2.approx.f16x2 softmax + MMA row-sums, bf16-split out
// ===========================================================================

#define S_LEN   2048
#define D_MODEL 2048
#define H_Q     32
#define KV_W    512
#define GK      2048
#define QSCALE  0.1803368801111244f   // 0.125 * log2(e)
#define ONES2   0x3C003C00u           // half2(1.0, 1.0)

// ------------------------------ scratch ------------------------------------
__device__ __align__(16) __half g_qh[S_LEN * D_MODEL];
__device__ __align__(16) __half g_kh[S_LEN * KV_W];
__device__ __align__(16) __half g_vh[S_LEN * KV_W];

__device__ __align__(16) __nv_bfloat16 g_ahi[S_LEN * D_MODEL];
__device__ __align__(16) __nv_bfloat16 g_alo[S_LEN * D_MODEL];
__device__ __align__(16) __nv_bfloat16 g_bhi[S_LEN * D_MODEL];
__device__ __align__(16) __nv_bfloat16 g_blo[S_LEN * D_MODEL];
__device__ __align__(16) __nv_bfloat16 g_chi[S_LEN * D_MODEL];
__device__ __align__(16) __nv_bfloat16 g_clo[S_LEN * D_MODEL];

__device__ __align__(16) __nv_bfloat16 g_wq_hi[D_MODEL * GK];
__device__ __align__(16) __nv_bfloat16 g_wq_lo[D_MODEL * GK];
__device__ __align__(16) __nv_bfloat16 g_wk_hi[KV_W * GK];
__device__ __align__(16) __nv_bfloat16 g_wk_lo[KV_W * GK];
__device__ __align__(16) __nv_bfloat16 g_wv_hi[KV_W * GK];
__device__ __align__(16) __nv_bfloat16 g_wv_lo[KV_W * GK];
__device__ __align__(16) __nv_bfloat16 g_wo_hi[D_MODEL * GK];
__device__ __align__(16) __nv_bfloat16 g_wo_lo[D_MODEL * GK];

// ------------------------------ helpers ------------------------------------
__device__ __forceinline__ uint32_t smem_u32(const void* p) {
    uint32_t a;
    asm("{ .reg .u64 t; cvta.to.shared.u64 t, %1; cvt.u32.u64 %0, t; }"
        : "=r"(a) : "l"(p));
    return a;
}

#define CP16(dst, src) \
    asm volatile("cp.async.cg.shared.global [%0], [%1], 16;" \
                 :: "r"(dst), "l"(src))
#define CPCOMMIT() asm volatile("cp.async.commit_group;" ::: "memory")
#define CPWAIT(n)  asm volatile("cp.async.wait_group %0;" :: "n"(n) : "memory")

__device__ __forceinline__ void ldsm_x4(uint32_t& r0, uint32_t& r1,
                                        uint32_t& r2, uint32_t& r3, uint32_t a) {
    asm volatile("ldmatrix.sync.aligned.m8n8.x4.shared.b16 {%0,%1,%2,%3}, [%4];"
                 : "=r"(r0), "=r"(r1), "=r"(r2), "=r"(r3) : "r"(a));
}
__device__ __forceinline__ void ldsm_x4t(uint32_t& r0, uint32_t& r1,
                                         uint32_t& r2, uint32_t& r3, uint32_t a) {
    asm volatile("ldmatrix.sync.aligned.m8n8.x4.trans.shared.b16 {%0,%1,%2,%3}, [%4];"
                 : "=r"(r0), "=r"(r1), "=r"(r2), "=r"(r3) : "r"(a));
}

__device__ __forceinline__ void mma_bf16(float* c, const uint32_t* a,
                                         uint32_t b0, uint32_t b1) {
    asm volatile("mma.sync.aligned.m16n8k16.row.col.f32.bf16.bf16.f32 "
                 "{%0,%1,%2,%3}, {%4,%5,%6,%7}, {%8,%9}, {%0,%1,%2,%3};"
                 : "+f"(c[0]), "+f"(c[1]), "+f"(c[2]), "+f"(c[3])
                 : "r"(a[0]), "r"(a[1]), "r"(a[2]), "r"(a[3]), "r"(b0), "r"(b1));
}
__device__ __forceinline__ void mma_f16(float* c, const uint32_t* a,
                                        uint32_t b0, uint32_t b1) {
    asm volatile("mma.sync.aligned.m16n8k16.row.col.f32.f16.f16.f32 "
                 "{%0,%1,%2,%3}, {%4,%5,%6,%7}, {%8,%9}, {%0,%1,%2,%3};"
                 : "+f"(c[0]), "+f"(c[1]), "+f"(c[2]), "+f"(c[3])
                 : "r"(a[0]), "r"(a[1]), "r"(a[2]), "r"(a[3]), "r"(b0), "r"(b1));
}

__device__ __forceinline__ uint32_t h2exp2(uint32_t x) {
    uint32_t r;
    asm("ex2.approx.f16x2 %0, %1;" : "=r"(r) : "r"(x));
    return r;
}
__device__ __forceinline__ uint32_t packh2(float a, float b) {
    __half2 h = __floats2half2_rn(a, b);
    return *reinterpret_cast<uint32_t*>(&h);
}

// ---------------------------------------------------------------------------
// prep: fused weight-split (z 0..3) + activation-split (z 4..6)
// grid (64, 64, 7), 256 threads
// ---------------------------------------------------------------------------
__global__ __launch_bounds__(256)
void prep(const float* __restrict__ Wq, const float* __restrict__ Wk,
          const float* __restrict__ Wv, const float* __restrict__ Wo,
          const float4* __restrict__ Qa, const float4* __restrict__ Ka,
          const float4* __restrict__ Va,
          __nv_bfloat16* __restrict__ qhi, __nv_bfloat16* __restrict__ qlo,
          __nv_bfloat16* __restrict__ khi, __nv_bfloat16* __restrict__ klo,
          __nv_bfloat16* __restrict__ vhi, __nv_bfloat16* __restrict__ vlo,
          __nv_bfloat16* __restrict__ ohi, __nv_bfloat16* __restrict__ olo,
          __nv_bfloat16* __restrict__ ahi, __nv_bfloat16* __restrict__ alo,
          __nv_bfloat16* __restrict__ bhi, __nv_bfloat16* __restrict__ blo,
          __nv_bfloat16* __restrict__ chi, __nv_bfloat16* __restrict__ clo)
{
    __shared__ float tile[32][33];
    const int z = blockIdx.z;
    if (z < 4) {
        // ---- weight transpose + split: W[K,N] fp32 -> hi/lo bf16 [N][K]
        const float* W;  __nv_bfloat16 *hi, *lo;  int Ncols;
        if      (z == 0) { W = Wq; hi = qhi; lo = qlo; Ncols = D_MODEL; }
        else if (z == 1) { W = Wk; hi = khi; lo = klo; Ncols = KV_W; }
        else if (z == 2) { W = Wv; hi = vhi; lo = vlo; Ncols = KV_W; }
        else             { W = Wo; hi = ohi; lo = olo; Ncols = D_MODEL; }

        const int bx = blockIdx.x, by = blockIdx.y;
        if (bx * 32 >= Ncols) return;
        const int tx = threadIdx.x & 31, ty = threadIdx.x >> 5;

        #pragma unroll
        for (int i = 0; i < 32; i += 8)
            tile[ty + i][tx] = W[(size_t)(by * 32 + ty + i) * Ncols + bx * 32 + tx];
        __syncthreads();
        #pragma unroll
        for (int i = 0; i < 32; i += 8) {
            const int n = bx * 32 + ty + i;
            const int k = by * 32 + tx;
            float x = tile[tx][ty + i];
            __nv_bfloat16 h = __float2bfloat16_rn(x);
            hi[(size_t)n * GK + k] = h;
            lo[(size_t)n * GK + k] = __float2bfloat16_rn(x - __bfloat162float(h));
        }
    } else {
        // ---- activation split (elementwise, float4)
        const float4* A;  __nv_bfloat16 *hi, *lo;
        if      (z == 4) { A = Qa; hi = ahi; lo = alo; }
        else if (z == 5) { A = Ka; hi = bhi; lo = blo; }
        else             { A = Va; hi = chi; lo = clo; }

        const int i = (blockIdx.y * 64 + blockIdx.x) * 256 + threadIdx.x;
        float4 v = A[i];
        __nv_bfloat162 h0 = __floats2bfloat162_rn(v.x, v.y);
        __nv_bfloat162 h1 = __floats2bfloat162_rn(v.z, v.w);
        __nv_bfloat162 l0 = __floats2bfloat162_rn(v.x - __bfloat162float(h0.x),
                                                  v.y - __bfloat162float(h0.y));
        __nv_bfloat162 l1 = __floats2bfloat162_rn(v.z - __bfloat162float(h1.x),
                                                  v.w - __bfloat162float(h1.y));
        uint2 uh = make_uint2(*(uint32_t*)&h0, *(uint32_t*)&h1);
        uint2 ul = make_uint2(*(uint32_t*)&l0, *(uint32_t*)&l1);
        *(uint2*)(hi + (size_t)i * 4) = uh;
        *(uint2*)(lo + (size_t)i * 4) = ul;
    }
}

// ---------------------------------------------------------------------------
// GEMM body: 128x128 tile, 4 warps, 3-stage, 2 CTA/SM
// ---------------------------------------------------------------------------
#define GSTAGE 32768

template <int MODE>
__device__ __forceinline__
void gemm_body(const __nv_bfloat16* __restrict__ Ahi, const __nv_bfloat16* __restrict__ Alo,
               const __nv_bfloat16* __restrict__ Bhi, const __nv_bfloat16* __restrict__ Blo,
               const float* __restrict__ bias, void* __restrict__ Cout,
               int Ntot, int m0, int n0, uint32_t sb)
{
    const int tid  = threadIdx.x;
    const int lane = tid & 31;
    const int wid  = tid >> 5;
    const int wm   = (wid & 1) * 64;
    const int wn   = (wid >> 1) * 64;
    const int gg   = lane >> 2, tg = lane & 3;
    const int mi   = lane >> 3;

    float acc[4][8][4];
    #pragma unroll
    for (int a = 0; a < 4; a++)
        #pragma unroll
        for (int b = 0; b < 8; b++)
            #pragma unroll
            for (int c = 0; c < 4; c++) acc[a][b][c] = 0.f;

    auto load_stage = [&](int it) {
        const uint32_t st = sb + (it % 3) * GSTAGE;
        const int k0 = it * 32;
        #pragma unroll
        for (int t = 0; t < 4; t++) {
            const int f   = tid + t * 128;
            const int row = f >> 2, c = f & 3;
            const uint32_t sw = row * 64 + ((c ^ ((row >> 1) & 3)) * 16);
            CP16(st + sw,         Ahi + (size_t)(m0 + row) * GK + k0 + c * 8);
            CP16(st + 8192 + sw,  Alo + (size_t)(m0 + row) * GK + k0 + c * 8);
            CP16(st + 16384 + sw, Bhi + (size_t)(n0 + row) * GK + k0 + c * 8);
            CP16(st + 24576 + sw, Blo + (size_t)(n0 + row) * GK + k0 + c * 8);
        }
    };

    load_stage(0); CPCOMMIT();
    load_stage(1); CPCOMMIT();

    const int NIT = GK / 32;
    for (int it = 0; it < NIT; it++) {
        if (it + 1 < NIT) { CPWAIT(1); } else { CPWAIT(0); }
        __syncthreads();
        const uint32_t st = sb + (it % 3) * GSTAGE;

        #pragma unroll
        for (int s = 0; s < 2; s++) {
            uint32_t aH[4][4], aL[4][4];
            #pragma unroll
            for (int mt = 0; mt < 4; mt++) {
                const int r = wm + mt * 16 + (mi & 1) * 8 + (lane & 7);
                const int c = 2 * s + (mi >> 1);
                const uint32_t ad = st + r * 64 + ((c ^ ((r >> 1) & 3)) * 16);
                ldsm_x4(aH[mt][0], aH[mt][1], aH[mt][2], aH[mt][3], ad);
                ldsm_x4(aL[mt][0], aL[mt][1], aL[mt][2], aL[mt][3], ad + 8192);
            }
            uint32_t bH[8][2], bL[8][2];
            #pragma unroll
            for (int nt = 0; nt < 4; nt++) {
                const int r = wn + nt * 16 + (mi >> 1) * 8 + (lane & 7);
                const int c = 2 * s + (mi & 1);
                const uint32_t bd = st + 16384 + r * 64 + ((c ^ ((r >> 1) & 3)) * 16);
                ldsm_x4(bH[2*nt][0], bH[2*nt][1], bH[2*nt+1][0], bH[2*nt+1][1], bd);
                ldsm_x4(bL[2*nt][0], bL[2*nt][1], bL[2*nt+1][0], bL[2*nt+1][1], bd + 8192);
            }
            #pragma unroll
            for (int mt = 0; mt < 4; mt++)
                #pragma unroll
                for (int n = 0; n < 8; n++) {
                    mma_bf16(acc[mt][n], aH[mt], bH[n][0], bH[n][1]);
                    mma_bf16(acc[mt][n], aH[mt], bL[n][0], bL[n][1]);
                    mma_bf16(acc[mt][n], aL[mt], bH[n][0], bH[n][1]);
                }
        }
        if (it + 2 < NIT) { load_stage(it + 2); CPCOMMIT(); }
    }

    #pragma unroll
    for (int mt = 0; mt < 4; mt++)
        #pragma unroll
        for (int n = 0; n < 8; n++) {
            const int r0  = m0 + wm + mt * 16 + gg;
            const int col = n0 + wn + n * 8 + tg * 2;
            const float b0 = bias[col], b1 = bias[col + 1];
            if (MODE == 0) {
                float* C = (float*)Cout;
                *(float2*)(C + (size_t)r0 * Ntot + col) =
                    make_float2(acc[mt][n][0] + b0, acc[mt][n][1] + b1);
                *(float2*)(C + (size_t)(r0 + 8) * Ntot + col) =
                    make_float2(acc[mt][n][2] + b0, acc[mt][n][3] + b1);
            } else {
                const float sc = (MODE == 2) ? QSCALE : 1.0f;
                __half* C = (__half*)Cout;
                __half2 h0 = __floats2half2_rn((acc[mt][n][0] + b0) * sc,
                                               (acc[mt][n][1] + b1) * sc);
                __half2 h1 = __floats2half2_rn((acc[mt][n][2] + b0) * sc,
                                               (acc[mt][n][3] + b1) * sc);
                *(__half2*)(C + (size_t)r0 * Ntot + col) = h0;
                *(__half2*)(C + (size_t)(r0 + 8) * Ntot + col) = h1;
            }
        }
}

__global__ __launch_bounds__(128, 2)
void gemm_qkv(const __nv_bfloat16* __restrict__ Qhi, const __nv_bfloat16* __restrict__ Qlo,
              const __nv_bfloat16* __restrict__ Khi, const __nv_bfloat16* __restrict__ Klo,
              const __nv_bfloat16* __restrict__ Vhi, const __nv_bfloat16* __restrict__ Vlo,
              const __nv_bfloat16* __restrict__ WQhi, const __nv_bfloat16* __restrict__ WQlo,
              const __nv_bfloat16* __restrict__ WKhi, const __nv_bfloat16* __restrict__ WKlo,
              const __nv_bfloat16* __restrict__ WVhi, const __nv_bfloat16* __restrict__ WVlo,
              const float* __restrict__ bq, const float* __restrict__ bk,
              const float* __restrict__ bv,
              __half* __restrict__ qh, __half* __restrict__ kh, __half* __restrict__ vh)
{
    extern __shared__ char sm[];
    const uint32_t sb = smem_u32(sm);
    const int bx = blockIdx.x;
    const int m0 = blockIdx.y * 128;
    if (bx < 16)
        gemm_body<2>(Qhi, Qlo, WQhi, WQlo, bq, qh, D_MODEL, m0, bx * 128, sb);
    else if (bx < 20)
        gemm_body<1>(Khi, Klo, WKhi, WKlo, bk, kh, KV_W, m0, (bx - 16) * 128, sb);
    else
        gemm_body<1>(Vhi, Vlo, WVhi, WVlo, bv, vh, KV_W, m0, (bx - 20) * 128, sb);
}

__global__ __launch_bounds__(128, 2)
void gemm_o(const __nv_bfloat16* __restrict__ Ahi, const __nv_bfloat16* __restrict__ Alo,
            const __nv_bfloat16* __restrict__ Bhi, const __nv_bfloat16* __restrict__ Blo,
            const float* __restrict__ bias, float* __restrict__ Cout)
{
    extern __shared__ char sm[];
    gemm_body<0>(Ahi, Alo, Bhi, Blo, bias, Cout, D_MODEL,
                 blockIdx.y * 128, blockIdx.x * 128, smem_u32(sm));
}

// ---------------------------------------------------------------------------
// fp16 HMMA causal flash attention.  q-tile 128/CTA, 4 warps (32 q-rows each),
// kv tile 64, 3-stage ring, ONE sync/iter.  ex2.approx.f16x2 softmax,
// MMA row-sums, s=0 V-fragment hoist.  Output bf16 hi/lo split.
// ---------------------------------------------------------------------------
__global__ __launch_bounds__(128)
void flash(const __half* __restrict__ qbuf, const __half* __restrict__ kbuf,
           const __half* __restrict__ vbuf,
           __nv_bfloat16* __restrict__ ohi, __nv_bfloat16* __restrict__ olo)
{
    __shared__ __align__(16) __half sQ[128 * 64];
    __shared__ __align__(16) __half sK[3][64 * 64];
    __shared__ __align__(16) __half sV[3][64 * 64];

    const int qt   = (int)gridDim.x - 1 - (int)blockIdx.x;
    const int h    = blockIdx.y;
    const int g    = h >> 2;
    const int tid  = threadIdx.x;
    const int warp = tid >> 5, lane = tid & 31;
    const int gg   = lane >> 2, tg = lane & 3;
    const int mi   = lane >> 3;
    const int q0   = qt * 128;
    const int wrow = q0 + warp * 32;

    const uint32_t qb  = smem_u32(sQ);
    const uint32_t kb0 = smem_u32(sK);
    const uint32_t vb0 = smem_u32(sV);

    #pragma unroll
    for (int i = 0; i < 8; i++) {
        const int f = tid + i * 128;
        const int r = f >> 3, c = f & 7;
        CP16(qb + r * 128 + ((c ^ (r & 7)) * 16),
             qbuf + (size_t)(q0 + r) * D_MODEL + h * 64 + c * 8);
    }
    auto loadKV = [&](int kt) {
        const uint32_t ko = kb0 + (kt % 3) * 8192;
        const uint32_t vo = vb0 + (kt % 3) * 8192;
        #pragma unroll
        for (int i = 0; i < 4; i++) {
            const int f = tid + i * 128;
            const int r = f >> 3, c = f & 7;
            const size_t src = (size_t)(kt * 64 + r) * KV_W + g * 64 + c * 8;
            const uint32_t d = r * 128 + ((c ^ (r & 7)) * 16);
            CP16(ko + d, kbuf + src);
            CP16(vo + d, vbuf + src);
        }
    };
    const int KT = 2 * qt + 2;
    loadKV(0); CPCOMMIT();            // group: Q + KV0
    if (KT > 1) loadKV(1);
    CPCOMMIT();                        // group: KV1 (possibly empty)
    CPWAIT(1);                         // Q + KV0 ready
    __syncthreads();

    uint32_t qa[4][2][4];
    #pragma unroll
    for (int mt = 0; mt < 2; mt++) {
        const int r = warp * 32 + mt * 16 + (mi & 1) * 8 + (lane & 7);
        #pragma unroll
        for (int s = 0; s < 4; s++) {
            const int c = 2 * s + (mi >> 1);
            ldsm_x4(qa[s][mt][0], qa[s][mt][1], qa[s][mt][2], qa[s][mt][3],
                    qb + r * 128 + ((c ^ (r & 7)) * 16));
        }
    }

    float o[2][8][4];
    #pragma unroll
    for (int mt = 0; mt < 2; mt++)
        #pragma unroll
        for (int n = 0; n < 8; n++)
            #pragma unroll
            for (int c = 0; c < 4; c++) o[mt][n][c] = 0.f;
    float mM[2][2] = {{-1e30f, -1e30f}, {-1e30f, -1e30f}};
    float lL[2][2] = {{0.f, 0.f}, {0.f, 0.f}};

    for (int kt = 0; kt < KT; kt++) {
        if (kt > 0) {
            if (kt + 1 < KT) { CPWAIT(1); } else { CPWAIT(0); }
            __syncthreads();
        }
        const uint32_t ko = kb0 + (kt % 3) * 8192;
        const uint32_t vo = vb0 + (kt % 3) * 8192;

        // ---- S = Q K^T ----
        float sc[2][8][4];
        #pragma unroll
        for (int mt = 0; mt < 2; mt++)
            #pragma unroll
            for (int n = 0; n < 8; n++)
                #pragma unroll
                for (int c = 0; c < 4; c++) sc[mt][n][c] = 0.f;

        #pragma unroll
        for (int s = 0; s < 4; s++) {
            uint32_t bfr[8][2];
            #pragma unroll
            for (int nt = 0; nt < 4; nt++) {
                const int r = nt * 16 + (mi >> 1) * 8 + (lane & 7);
                const int c = 2 * s + (mi & 1);
                ldsm_x4(bfr[2*nt][0], bfr[2*nt][1], bfr[2*nt+1][0], bfr[2*nt+1][1],
                        ko + r * 128 + ((c ^ (r & 7)) * 16));
            }
            #pragma unroll
            for (int mt = 0; mt < 2; mt++)
                #pragma unroll
                for (int n = 0; n < 8; n++)
                    mma_f16(sc[mt][n], qa[s][mt], bfr[n][0], bfr[n][1]);
        }

        // ---- hoist s=0 V fragments (overlaps softmax latency) ----
        uint32_t vf0[8][2];
        #pragma unroll
        for (int nt = 0; nt < 4; nt++) {
            const int r = (mi & 1) * 8 + (lane & 7);
            const int c = 2 * nt + (mi >> 1);
            ldsm_x4t(vf0[2*nt][0], vf0[2*nt][1], vf0[2*nt+1][0], vf0[2*nt+1][1],
                     vo + r * 128 + ((c ^ (r & 7)) * 16));
        }

        // causal mask
        if (kt * 64 + 63 > wrow) {
            #pragma unroll
            for (int mt = 0; mt < 2; mt++) {
                const int r0 = wrow + mt * 16 + gg;
                const int r1 = r0 + 8;
                #pragma unroll
                for (int n = 0; n < 8; n++) {
                    const int col = kt * 64 + n * 8 + tg * 2;
                    if (col     > r0) sc[mt][n][0] = -1e30f;
                    if (col + 1 > r0) sc[mt][n][1] = -1e30f;
                    if (col     > r1) sc[mt][n][2] = -1e30f;
                    if (col + 1 > r1) sc[mt][n][3] = -1e30f;
                }
            }
        }

        // ---- online softmax: P = ex2.approx.f16x2(sc - mn), l via MMA ----
        uint32_t pa[2][4][4];
        #pragma unroll
        for (int mt = 0; mt < 2; mt++) {
            float mx0 = -1e30f, mx1 = -1e30f;
            #pragma unroll
            for (int n = 0; n < 8; n++) {
                mx0 = fmaxf(mx0, fmaxf(sc[mt][n][0], sc[mt][n][1]));
                mx1 = fmaxf(mx1, fmaxf(sc[mt][n][2], sc[mt][n][3]));
            }
            mx0 = fmaxf(mx0, __shfl_xor_sync(0xffffffffu, mx0, 1));
            mx0 = fmaxf(mx0, __shfl_xor_sync(0xffffffffu, mx0, 2));
            mx1 = fmaxf(mx1, __shfl_xor_sync(0xffffffffu, mx1, 1));
            mx1 = fmaxf(mx1, __shfl_xor_sync(0xffffffffu, mx1, 2));
            const float mn0 = fmaxf(mM[mt][0], mx0);
            const float mn1 = fmaxf(mM[mt][1], mx1);
            const float c0 = exp2f(mM[mt][0] - mn0);
            const float c1 = exp2f(mM[mt][1] - mn1);
            mM[mt][0] = mn0; mM[mt][1] = mn1;

            #pragma unroll
            for (int s = 0; s < 4; s++) {
                pa[mt][s][0] = h2exp2(packh2(sc[mt][2*s][0]   - mn0, sc[mt][2*s][1]   - mn0));
                pa[mt][s][1] = h2exp2(packh2(sc[mt][2*s][2]   - mn1, sc[mt][2*s][3]   - mn1));
                pa[mt][s][2] = h2exp2(packh2(sc[mt][2*s+1][0] - mn0, sc[mt][2*s+1][1] - mn0));
                pa[mt][s][3] = h2exp2(packh2(sc[mt][2*s+1][2] - mn1, sc[mt][2*s+1][3] - mn1));
            }

            float lacc[4] = {0.f, 0.f, 0.f, 0.f};
            #pragma unroll
            for (int s = 0; s < 4; s++)
                mma_f16(lacc, pa[mt][s], ONES2, ONES2);
            lL[mt][0] = lL[mt][0] * c0 + lacc[0];
            lL[mt][1] = lL[mt][1] * c1 + lacc[2];

            #pragma unroll
            for (int n = 0; n < 8; n++) {
                o[mt][n][0] *= c0; o[mt][n][1] *= c0;
                o[mt][n][2] *= c1; o[mt][n][3] *= c1;
            }
        }

        // ---- O += P V  (s=0 uses hoisted fragments) ----
        #pragma unroll
        for (int mt = 0; mt < 2; mt++)
            #pragma unroll
            for (int n = 0; n < 8; n++)
                mma_f16(o[mt][n], pa[mt][0], vf0[n][0], vf0[n][1]);

        #pragma unroll
        for (int s = 1; s < 4; s++) {
            uint32_t vfr[8][2];
            #pragma unroll
            for (int nt = 0; nt < 4; nt++) {
                const int r = s * 16 + (mi & 1) * 8 + (lane & 7);
                const int c = 2 * nt + (mi >> 1);
                ldsm_x4t(vfr[2*nt][0], vfr[2*nt][1], vfr[2*nt+1][0], vfr[2*nt+1][1],
                         vo + r * 128 + ((c ^ (r & 7)) * 16));
            }
            #pragma unroll
            for (int mt = 0; mt < 2; mt++)
                #pragma unroll
                for (int n = 0; n < 8; n++)
                    mma_f16(o[mt][n], pa[mt][s], vfr[n][0], vfr[n][1]);
        }

        if (kt + 2 < KT) { loadKV(kt + 2); CPCOMMIT(); }
    }

    // finalize: normalize, split bf16 hi/lo, store
    #pragma unroll
    for (int mt = 0; mt < 2; mt++) {
        const float i0 = 1.f / lL[mt][0], i1 = 1.f / lL[mt][1];
        const int r0 = wrow + mt * 16 + gg;
        const int r1 = r0 + 8;
        #pragma unroll
        for (int n = 0; n < 8; n++) {
            const int col = h * 64 + n * 8 + tg * 2;
            float v0 = o[mt][n][0] * i0, v1 = o[mt][n][1] * i0;
            float v2 = o[mt][n][2] * i1, v3 = o[mt][n][3] * i1;
            __nv_bfloat162 h0 = __floats2bfloat162_rn(v0, v1);
            __nv_bfloat162 h1 = __floats2bfloat162_rn(v2, v3);
            __nv_bfloat162 e0 = __floats2bfloat162_rn(v0 - __bfloat162float(h0.x),
                                                      v1 - __bfloat162float(h0.y));
            __nv_bfloat162 e1 = __floats2bfloat162_rn(v2 - __bfloat162float(h1.x),
                                                      v3 - __bfloat162float(h1.y));
            *(uint32_t*)(ohi + (size_t)r0 * D_MODEL + col) = *(uint32_t*)&h0;
            *(uint32_t*)(olo + (size_t)r0 * D_MODEL + col) = *(uint32_t*)&e0;
            *(uint32_t*)(ohi + (size_t)r1 * D_MODEL + col) = *(uint32_t*)&h1;
            *(uint32_t*)(olo + (size_t)r1 * D_MODEL + col) = *(uint32_t*)&e1;
        }
    }
}

// ---------------------------------------------------------------------------
// Launch
// ---------------------------------------------------------------------------
extern "C" void kernel_launch(void* const* d_in, const int* in_sizes, int n_in,
                              void* d_out, int out_size)
{
    const float* queries = (const float*)d_in[0];
    const float* keys    = (const float*)d_in[1];
    const float* values  = (const float*)d_in[2];
    const float* Wq      = (const float*)d_in[3];
    const float* bq      = (const float*)d_in[4];
    const float* Wk      = (const float*)d_in[5];
    const float* bk      = (const float*)d_in[6];
    const float* Wv      = (const float*)d_in[7];
    const float* bv      = (const float*)d_in[8];
    const float* Wo      = (const float*)d_in[9];
    const float* bo      = (const float*)d_in[10];
    float*       out     = (float*)d_out;

    __half *qh, *kh, *vh;
    __nv_bfloat16 *ahi, *alo, *bhi, *blo, *chi, *clo;
    __nv_bfloat16 *wqh, *wql, *wkh, *wkl, *wvh, *wvl, *woh, *wol;
    cudaGetSymbolAddress((void**)&qh,  g_qh);
    cudaGetSymbolAddress((void**)&kh,  g_kh);
    cudaGetSymbolAddress((void**)&vh,  g_vh);
    cudaGetSymbolAddress((void**)&ahi, g_ahi);
    cudaGetSymbolAddress((void**)&alo, g_alo);
    cudaGetSymbolAddress((void**)&bhi, g_bhi);
    cudaGetSymbolAddress((void**)&blo, g_blo);
    cudaGetSymbolAddress((void**)&chi, g_chi);
    cudaGetSymbolAddress((void**)&clo, g_clo);
    cudaGetSymbolAddress((void**)&wqh, g_wq_hi);
    cudaGetSymbolAddress((void**)&wql, g_wq_lo);
    cudaGetSymbolAddress((void**)&wkh, g_wk_hi);
    cudaGetSymbolAddress((void**)&wkl, g_wk_lo);
    cudaGetSymbolAddress((void**)&wvh, g_wv_hi);
    cudaGetSymbolAddress((void**)&wvl, g_wv_lo);
    cudaGetSymbolAddress((void**)&woh, g_wo_hi);
    cudaGetSymbolAddress((void**)&wol, g_wo_lo);

    cudaFuncSetAttribute(gemm_qkv, cudaFuncAttributeMaxDynamicSharedMemorySize, 3 * GSTAGE);
    cudaFuncSetAttribute(gemm_o,   cudaFuncAttributeMaxDynamicSharedMemorySize, 3 * GSTAGE);

    // fused weight + activation prep
    prep<<<dim3(64, 64, 7), 256>>>(
        Wq, Wk, Wv, Wo,
        (const float4*)queries, (const float4*)keys, (const float4*)values,
        wqh, wql, wkh, wkl, wvh, wvl, woh, wol,
        ahi, alo, bhi, blo, chi, clo);

    // Q + K + V projections fused
    gemm_qkv<<<dim3(24, S_LEN / 128), 128, 3 * GSTAGE>>>(
        ahi, alo, bhi, blo, chi, clo,
        wqh, wql, wkh, wkl, wvh, wvl,
        bq, bk, bv, qh, kh, vh);

    // causal GQA flash attention -> bf16 hi/lo split output
    flash<<<dim3(S_LEN / 128, H_Q), 128>>>(qh, kh, vh, ahi, alo);

    // output projection
    gemm_o<<<dim3(D_MODEL / 128, S_LEN / 128), 128, 3 * GSTAGE>>>(
        ahi, alo, woh, wol, bo, out);
}

// round 10
// speedup vs baseline: 1.3402x; 1.2910x over previous
#include <cuda_runtime.h>
#include <cuda_bf16.h>
#include <cuda_fp16.h>
#include <cstdint>

// ===========================================================================
// GQA layer, sm_103 baseline-PTX path: mma.sync (HMMA) everywhere.
//   - projections: fp16 2-pass GEMM (A split hi/lo fp16, W single fp16),
//       CTA tile 128x128 (4 warps, 64x64 each), 4-stage cp.async, 2 CTAs/SM
//   - attention:   fp16 FA-2, q-tile 128/CTA, 4 warps, 3-stage KV ring,
//       ex2.approx.f16x2 softmax + MMA row-sums, fp16-split output
// ===========================================================================

#define S_LEN   2048
#define D_MODEL 2048
#define H_Q     32
#define KV_W    512
#define GK      2048
#define QSCALE  0.1803368801111244f   // 0.125 * log2(e)
#define ONES2   0x3C003C00u           // half2(1.0, 1.0)

// ------------------------------ scratch ------------------------------------
__device__ __align__(16) __half g_qh[S_LEN * D_MODEL];
__device__ __align__(16) __half g_kh[S_LEN * KV_W];
__device__ __align__(16) __half g_vh[S_LEN * KV_W];

// fp16 split activations: A (queries / attn-out), B (keys), C (values)
__device__ __align__(16) __half g_ahi[S_LEN * D_MODEL];
__device__ __align__(16) __half g_alo[S_LEN * D_MODEL];
__device__ __align__(16) __half g_bhi[S_LEN * D_MODEL];
__device__ __align__(16) __half g_blo[S_LEN * D_MODEL];
__device__ __align__(16) __half g_chi[S_LEN * D_MODEL];
__device__ __align__(16) __half g_clo[S_LEN * D_MODEL];

// transposed weights, single fp16, [N][K]
__device__ __align__(16) __half g_wq[D_MODEL * GK];
__device__ __align__(16) __half g_wk[KV_W * GK];
__device__ __align__(16) __half g_wv[KV_W * GK];
__device__ __align__(16) __half g_wo[D_MODEL * GK];

// ------------------------------ helpers ------------------------------------
__device__ __forceinline__ uint32_t smem_u32(const void* p) {
    uint32_t a;
    asm("{ .reg .u64 t; cvta.to.shared.u64 t, %1; cvt.u32.u64 %0, t; }"
        : "=r"(a) : "l"(p));
    return a;
}

#define CP16(dst, src) \
    asm volatile("cp.async.cg.shared.global [%0], [%1], 16;" \
                 :: "r"(dst), "l"(src))
#define CPCOMMIT() asm volatile("cp.async.commit_group;" ::: "memory")
#define CPWAIT(n)  asm volatile("cp.async.wait_group %0;" :: "n"(n) : "memory")

__device__ __forceinline__ void ldsm_x4(uint32_t& r0, uint32_t& r1,
                                        uint32_t& r2, uint32_t& r3, uint32_t a) {
    asm volatile("ldmatrix.sync.aligned.m8n8.x4.shared.b16 {%0,%1,%2,%3}, [%4];"
                 : "=r"(r0), "=r"(r1), "=r"(r2), "=r"(r3) : "r"(a));
}
__device__ __forceinline__ void ldsm_x4t(uint32_t& r0, uint32_t& r1,
                                         uint32_t& r2, uint32_t& r3, uint32_t a) {
    asm volatile("ldmatrix.sync.aligned.m8n8.x4.trans.shared.b16 {%0,%1,%2,%3}, [%4];"
                 : "=r"(r0), "=r"(r1), "=r"(r2), "=r"(r3) : "r"(a));
}

__device__ __forceinline__ void mma_f16(float* c, const uint32_t* a,
                                        uint32_t b0, uint32_t b1) {
    asm volatile("mma.sync.aligned.m16n8k16.row.col.f32.f16.f16.f32 "
                 "{%0,%1,%2,%3}, {%4,%5,%6,%7}, {%8,%9}, {%0,%1,%2,%3};"
                 : "+f"(c[0]), "+f"(c[1]), "+f"(c[2]), "+f"(c[3])
                 : "r"(a[0]), "r"(a[1]), "r"(a[2]), "r"(a[3]), "r"(b0), "r"(b1));
}

__device__ __forceinline__ uint32_t h2exp2(uint32_t x) {
    uint32_t r;
    asm("ex2.approx.f16x2 %0, %1;" : "=r"(r) : "r"(x));
    return r;
}
__device__ __forceinline__ uint32_t packh2(float a, float b) {
    __half2 h = __floats2half2_rn(a, b);
    return *reinterpret_cast<uint32_t*>(&h);
}

// ---------------------------------------------------------------------------
// prep: fused weight transpose->fp16 (z 0..3) + activation fp16-split (z 4..6)
// grid (64, 64, 7), 256 threads
// ---------------------------------------------------------------------------
__global__ __launch_bounds__(256)
void prep(const float* __restrict__ Wq, const float* __restrict__ Wk,
          const float* __restrict__ Wv, const float* __restrict__ Wo,
          const float4* __restrict__ Qa, const float4* __restrict__ Ka,
          const float4* __restrict__ Va,
          __half* __restrict__ wq, __half* __restrict__ wk,
          __half* __restrict__ wv, __half* __restrict__ wo,
          __half* __restrict__ ahi, __half* __restrict__ alo,
          __half* __restrict__ bhi, __half* __restrict__ blo,
          __half* __restrict__ chi, __half* __restrict__ clo)
{
    __shared__ float tile[32][33];
    const int z = blockIdx.z;
    if (z < 4) {
        const float* W;  __half* dst;  int Ncols;
        if      (z == 0) { W = Wq; dst = wq; Ncols = D_MODEL; }
        else if (z == 1) { W = Wk; dst = wk; Ncols = KV_W; }
        else if (z == 2) { W = Wv; dst = wv; Ncols = KV_W; }
        else             { W = Wo; dst = wo; Ncols = D_MODEL; }

        const int bx = blockIdx.x, by = blockIdx.y;
        if (bx * 32 >= Ncols) return;
        const int tx = threadIdx.x & 31, ty = threadIdx.x >> 5;

        #pragma unroll
        for (int i = 0; i < 32; i += 8)
            tile[ty + i][tx] = W[(size_t)(by * 32 + ty + i) * Ncols + bx * 32 + tx];
        __syncthreads();
        #pragma unroll
        for (int i = 0; i < 32; i += 8) {
            const int n = bx * 32 + ty + i;
            const int k = by * 32 + tx;
            dst[(size_t)n * GK + k] = __float2half_rn(tile[tx][ty + i]);
        }
    } else {
        const float4* A;  __half *hi, *lo;
        if      (z == 4) { A = Qa; hi = ahi; lo = alo; }
        else if (z == 5) { A = Ka; hi = bhi; lo = blo; }
        else             { A = Va; hi = chi; lo = clo; }

        const int i = (blockIdx.y * 64 + blockIdx.x) * 256 + threadIdx.x;
        float4 v = A[i];
        __half2 h0 = __floats2half2_rn(v.x, v.y);
        __half2 h1 = __floats2half2_rn(v.z, v.w);
        __half2 l0 = __floats2half2_rn(v.x - __half2float(h0.x),
                                       v.y - __half2float(h0.y));
        __half2 l1 = __floats2half2_rn(v.z - __half2float(h1.x),
                                       v.w - __half2float(h1.y));
        uint2 uh = make_uint2(*(uint32_t*)&h0, *(uint32_t*)&h1);
        uint2 ul = make_uint2(*(uint32_t*)&l0, *(uint32_t*)&l1);
        *(uint2*)(hi + (size_t)i * 4) = uh;
        *(uint2*)(lo + (size_t)i * 4) = ul;
    }
}

// ---------------------------------------------------------------------------
// GEMM body: C[128x128] = (Ah+Al) @ B^T + bias, fp16 2-pass.
// BK=32, 128 thr, 4 warps (2m x 2n), warp tile 64x64.
// Stage: Ah(8K) Al(8K) B(8K) = 24KB; 4 stages = 96KB -> 2 CTAs/SM.
// MODE 0: float out; MODE 1: half out; MODE 2: half out * QSCALE.
// ---------------------------------------------------------------------------
#define GSTAGE 24576

template <int MODE>
__device__ __forceinline__
void gemm_body(const __half* __restrict__ Ahi, const __half* __restrict__ Alo,
               const __half* __restrict__ B, const float* __restrict__ bias,
               void* __restrict__ Cout, int Ntot, int m0, int n0, uint32_t sb)
{
    const int tid  = threadIdx.x;
    const int lane = tid & 31;
    const int wid  = tid >> 5;
    const int wm   = (wid & 1) * 64;
    const int wn   = (wid >> 1) * 64;
    const int gg   = lane >> 2, tg = lane & 3;
    const int mi   = lane >> 3;

    float acc[4][8][4];
    #pragma unroll
    for (int a = 0; a < 4; a++)
        #pragma unroll
        for (int b = 0; b < 8; b++)
            #pragma unroll
            for (int c = 0; c < 4; c++) acc[a][b][c] = 0.f;

    auto load_stage = [&](int it) {
        const uint32_t st = sb + (it & 3) * GSTAGE;
        const int k0 = it * 32;
        #pragma unroll
        for (int t = 0; t < 4; t++) {
            const int f   = tid + t * 128;
            const int row = f >> 2, c = f & 3;
            const uint32_t sw = row * 64 + ((c ^ ((row >> 1) & 3)) * 16);
            CP16(st + sw,         Ahi + (size_t)(m0 + row) * GK + k0 + c * 8);
            CP16(st + 8192 + sw,  Alo + (size_t)(m0 + row) * GK + k0 + c * 8);
            CP16(st + 16384 + sw, B   + (size_t)(n0 + row) * GK + k0 + c * 8);
        }
    };

    load_stage(0); CPCOMMIT();
    load_stage(1); CPCOMMIT();
    load_stage(2); CPCOMMIT();

    const int NIT = GK / 32;
    for (int it = 0; it < NIT; it++) {
        if      (it + 2 < NIT) { CPWAIT(2); }
        else if (it + 1 < NIT) { CPWAIT(1); }
        else                   { CPWAIT(0); }
        __syncthreads();
        const uint32_t st = sb + (it & 3) * GSTAGE;

        #pragma unroll
        for (int s = 0; s < 2; s++) {
            uint32_t aH[4][4], aL[4][4];
            #pragma unroll
            for (int mt = 0; mt < 4; mt++) {
                const int r = wm + mt * 16 + (mi & 1) * 8 + (lane & 7);
                const int c = 2 * s + (mi >> 1);
                const uint32_t ad = st + r * 64 + ((c ^ ((r >> 1) & 3)) * 16);
                ldsm_x4(aH[mt][0], aH[mt][1], aH[mt][2], aH[mt][3], ad);
                ldsm_x4(aL[mt][0], aL[mt][1], aL[mt][2], aL[mt][3], ad + 8192);
            }
            uint32_t bF[8][2];
            #pragma unroll
            for (int nt = 0; nt < 4; nt++) {
                const int r = wn + nt * 16 + (mi >> 1) * 8 + (lane & 7);
                const int c = 2 * s + (mi & 1);
                const uint32_t bd = st + 16384 + r * 64 + ((c ^ ((r >> 1) & 3)) * 16);
                ldsm_x4(bF[2*nt][0], bF[2*nt][1], bF[2*nt+1][0], bF[2*nt+1][1], bd);
            }
            #pragma unroll
            for (int mt = 0; mt < 4; mt++)
                #pragma unroll
                for (int n = 0; n < 8; n++) {
                    mma_f16(acc[mt][n], aH[mt], bF[n][0], bF[n][1]);
                    mma_f16(acc[mt][n], aL[mt], bF[n][0], bF[n][1]);
                }
        }
        if (it + 3 < NIT) { load_stage(it + 3); CPCOMMIT(); }
    }

    #pragma unroll
    for (int mt = 0; mt < 4; mt++)
        #pragma unroll
        for (int n = 0; n < 8; n++) {
            const int r0  = m0 + wm + mt * 16 + gg;
            const int col = n0 + wn + n * 8 + tg * 2;
            const float b0 = bias[col], b1 = bias[col + 1];
            if (MODE == 0) {
                float* C = (float*)Cout;
                *(float2*)(C + (size_t)r0 * Ntot + col) =
                    make_float2(acc[mt][n][0] + b0, acc[mt][n][1] + b1);
                *(float2*)(C + (size_t)(r0 + 8) * Ntot + col) =
                    make_float2(acc[mt][n][2] + b0, acc[mt][n][3] + b1);
            } else {
                const float sc = (MODE == 2) ? QSCALE : 1.0f;
                __half* C = (__half*)Cout;
                __half2 h0 = __floats2half2_rn((acc[mt][n][0] + b0) * sc,
                                               (acc[mt][n][1] + b1) * sc);
                __half2 h1 = __floats2half2_rn((acc[mt][n][2] + b0) * sc,
                                               (acc[mt][n][3] + b1) * sc);
                *(__half2*)(C + (size_t)r0 * Ntot + col) = h0;
                *(__half2*)(C + (size_t)(r0 + 8) * Ntot + col) = h1;
            }
        }
}

__global__ __launch_bounds__(128, 2)
void gemm_qkv(const __half* __restrict__ Qhi, const __half* __restrict__ Qlo,
              const __half* __restrict__ Khi, const __half* __restrict__ Klo,
              const __half* __restrict__ Vhi, const __half* __restrict__ Vlo,
              const __half* __restrict__ WQ, const __half* __restrict__ WK,
              const __half* __restrict__ WV,
              const float* __restrict__ bq, const float* __restrict__ bk,
              const float* __restrict__ bv,
              __half* __restrict__ qh, __half* __restrict__ kh, __half* __restrict__ vh)
{
    extern __shared__ char sm[];
    const uint32_t sb = smem_u32(sm);
    const int bx = blockIdx.x;
    const int m0 = blockIdx.y * 128;
    if (bx < 16)
        gemm_body<2>(Qhi, Qlo, WQ, bq, qh, D_MODEL, m0, bx * 128, sb);
    else if (bx < 20)
        gemm_body<1>(Khi, Klo, WK, bk, kh, KV_W, m0, (bx - 16) * 128, sb);
    else
        gemm_body<1>(Vhi, Vlo, WV, bv, vh, KV_W, m0, (bx - 20) * 128, sb);
}

__global__ __launch_bounds__(128, 2)
void gemm_o(const __half* __restrict__ Ahi, const __half* __restrict__ Alo,
            const __half* __restrict__ B, const float* __restrict__ bias,
            float* __restrict__ Cout)
{
    extern __shared__ char sm[];
    gemm_body<0>(Ahi, Alo, B, bias, Cout, D_MODEL,
                 blockIdx.y * 128, blockIdx.x * 128, smem_u32(sm));
}

// ---------------------------------------------------------------------------
// fp16 HMMA causal flash attention.  q-tile 128/CTA, 4 warps (32 q-rows each),
// kv tile 64, 3-stage ring, ONE sync/iter.  ex2.approx.f16x2 softmax,
// MMA row-sums, s=0 V-fragment hoist.  Output fp16 hi/lo split.
// ---------------------------------------------------------------------------
__global__ __launch_bounds__(128)
void flash(const __half* __restrict__ qbuf, const __half* __restrict__ kbuf,
           const __half* __restrict__ vbuf,
           __half* __restrict__ ohi, __half* __restrict__ olo)
{
    __shared__ __align__(16) __half sQ[128 * 64];
    __shared__ __align__(16) __half sK[3][64 * 64];
    __shared__ __align__(16) __half sV[3][64 * 64];

    const int qt   = (int)gridDim.x - 1 - (int)blockIdx.x;
    const int h    = blockIdx.y;
    const int g    = h >> 2;
    const int tid  = threadIdx.x;
    const int warp = tid >> 5, lane = tid & 31;
    const int gg   = lane >> 2, tg = lane & 3;
    const int mi   = lane >> 3;
    const int q0   = qt * 128;
    const int wrow = q0 + warp * 32;

    const uint32_t qb  = smem_u32(sQ);
    const uint32_t kb0 = smem_u32(sK);
    const uint32_t vb0 = smem_u32(sV);

    #pragma unroll
    for (int i = 0; i < 8; i++) {
        const int f = tid + i * 128;
        const int r = f >> 3, c = f & 7;
        CP16(qb + r * 128 + ((c ^ (r & 7)) * 16),
             qbuf + (size_t)(q0 + r) * D_MODEL + h * 64 + c * 8);
    }
    auto loadKV = [&](int kt) {
        const uint32_t ko = kb0 + (kt % 3) * 8192;
        const uint32_t vo = vb0 + (kt % 3) * 8192;
        #pragma unroll
        for (int i = 0; i < 4; i++) {
            const int f = tid + i * 128;
            const int r = f >> 3, c = f & 7;
            const size_t src = (size_t)(kt * 64 + r) * KV_W + g * 64 + c * 8;
            const uint32_t d = r * 128 + ((c ^ (r & 7)) * 16);
            CP16(ko + d, kbuf + src);
            CP16(vo + d, vbuf + src);
        }
    };
    const int KT = 2 * qt + 2;
    loadKV(0); CPCOMMIT();
    if (KT > 1) loadKV(1);
    CPCOMMIT();
    CPWAIT(1);
    __syncthreads();

    uint32_t qa[4][2][4];
    #pragma unroll
    for (int mt = 0; mt < 2; mt++) {
        const int r = warp * 32 + mt * 16 + (mi & 1) * 8 + (lane & 7);
        #pragma unroll
        for (int s = 0; s < 4; s++) {
            const int c = 2 * s + (mi >> 1);
            ldsm_x4(qa[s][mt][0], qa[s][mt][1], qa[s][mt][2], qa[s][mt][3],
                    qb + r * 128 + ((c ^ (r & 7)) * 16));
        }
    }

    float o[2][8][4];
    #pragma unroll
    for (int mt = 0; mt < 2; mt++)
        #pragma unroll
        for (int n = 0; n < 8; n++)
            #pragma unroll
            for (int c = 0; c < 4; c++) o[mt][n][c] = 0.f;
    float mM[2][2] = {{-1e30f, -1e30f}, {-1e30f, -1e30f}};
    float lL[2][2] = {{0.f, 0.f}, {0.f, 0.f}};

    for (int kt = 0; kt < KT; kt++) {
        if (kt > 0) {
            if (kt + 1 < KT) { CPWAIT(1); } else { CPWAIT(0); }
            __syncthreads();
        }
        const uint32_t ko = kb0 + (kt % 3) * 8192;
        const uint32_t vo = vb0 + (kt % 3) * 8192;

        float sc[2][8][4];
        #pragma unroll
        for (int mt = 0; mt < 2; mt++)
            #pragma unroll
            for (int n = 0; n < 8; n++)
                #pragma unroll
                for (int c = 0; c < 4; c++) sc[mt][n][c] = 0.f;

        #pragma unroll
        for (int s = 0; s < 4; s++) {
            uint32_t bfr[8][2];
            #pragma unroll
            for (int nt = 0; nt < 4; nt++) {
                const int r = nt * 16 + (mi >> 1) * 8 + (lane & 7);
                const int c = 2 * s + (mi & 1);
                ldsm_x4(bfr[2*nt][0], bfr[2*nt][1], bfr[2*nt+1][0], bfr[2*nt+1][1],
                        ko + r * 128 + ((c ^ (r & 7)) * 16));
            }
            #pragma unroll
            for (int mt = 0; mt < 2; mt++)
                #pragma unroll
                for (int n = 0; n < 8; n++)
                    mma_f16(sc[mt][n], qa[s][mt], bfr[n][0], bfr[n][1]);
        }

        uint32_t vf0[8][2];
        #pragma unroll
        for (int nt = 0; nt < 4; nt++) {
            const int r = (mi & 1) * 8 + (lane & 7);
            const int c = 2 * nt + (mi >> 1);
            ldsm_x4t(vf0[2*nt][0], vf0[2*nt][1], vf0[2*nt+1][0], vf0[2*nt+1][1],
                     vo + r * 128 + ((c ^ (r & 7)) * 16));
        }

        if (kt * 64 + 63 > wrow) {
            #pragma unroll
            for (int mt = 0; mt < 2; mt++) {
                const int r0 = wrow + mt * 16 + gg;
                const int r1 = r0 + 8;
                #pragma unroll
                for (int n = 0; n < 8; n++) {
                    const int col = kt * 64 + n * 8 + tg * 2;
                    if (col     > r0) sc[mt][n][0] = -1e30f;
                    if (col + 1 > r0) sc[mt][n][1] = -1e30f;
                    if (col     > r1) sc[mt][n][2] = -1e30f;
                    if (col + 1 > r1) sc[mt][n][3] = -1e30f;
                }
            }
        }

        uint32_t pa[2][4][4];
        #pragma unroll
        for (int mt = 0; mt < 2; mt++) {
            float mx0 = -1e30f, mx1 = -1e30f;
            #pragma unroll
            for (int n = 0; n < 8; n++) {
                mx0 = fmaxf(mx0, fmaxf(sc[mt][n][0], sc[mt][n][1]));
                mx1 = fmaxf(mx1, fmaxf(sc[mt][n][2], sc[mt][n][3]));
            }
            mx0 = fmaxf(mx0, __shfl_xor_sync(0xffffffffu, mx0, 1));
            mx0 = fmaxf(mx0, __shfl_xor_sync(0xffffffffu, mx0, 2));
            mx1 = fmaxf(mx1, __shfl_xor_sync(0xffffffffu, mx1, 1));
            mx1 = fmaxf(mx1, __shfl_xor_sync(0xffffffffu, mx1, 2));
            const float mn0 = fmaxf(mM[mt][0], mx0);
            const float mn1 = fmaxf(mM[mt][1], mx1);
            const float c0 = exp2f(mM[mt][0] - mn0);
            const float c1 = exp2f(mM[mt][1] - mn1);
            mM[mt][0] = mn0; mM[mt][1] = mn1;

            #pragma unroll
            for (int s = 0; s < 4; s++) {
                pa[mt][s][0] = h2exp2(packh2(sc[mt][2*s][0]   - mn0, sc[mt][2*s][1]   - mn0));
                pa[mt][s][1] = h2exp2(packh2(sc[mt][2*s][2]   - mn1, sc[mt][2*s][3]   - mn1));
                pa[mt][s][2] = h2exp2(packh2(sc[mt][2*s+1][0] - mn0, sc[mt][2*s+1][1] - mn0));
                pa[mt][s][3] = h2exp2(packh2(sc[mt][2*s+1][2] - mn1, sc[mt][2*s+1][3] - mn1));
            }

            float lacc[4] = {0.f, 0.f, 0.f, 0.f};
            #pragma unroll
            for (int s = 0; s < 4; s++)
                mma_f16(lacc, pa[mt][s], ONES2, ONES2);
            lL[mt][0] = lL[mt][0] * c0 + lacc[0];
            lL[mt][1] = lL[mt][1] * c1 + lacc[2];

            #pragma unroll
            for (int n = 0; n < 8; n++) {
                o[mt][n][0] *= c0; o[mt][n][1] *= c0;
                o[mt][n][2] *= c1; o[mt][n][3] *= c1;
            }
        }

        #pragma unroll
        for (int mt = 0; mt < 2; mt++)
            #pragma unroll
            for (int n = 0; n < 8; n++)
                mma_f16(o[mt][n], pa[mt][0], vf0[n][0], vf0[n][1]);

        #pragma unroll
        for (int s = 1; s < 4; s++) {
            uint32_t vfr[8][2];
            #pragma unroll
            for (int nt = 0; nt < 4; nt++) {
                const int r = s * 16 + (mi & 1) * 8 + (lane & 7);
                const int c = 2 * nt + (mi >> 1);
                ldsm_x4t(vfr[2*nt][0], vfr[2*nt][1], vfr[2*nt+1][0], vfr[2*nt+1][1],
                         vo + r * 128 + ((c ^ (r & 7)) * 16));
            }
            #pragma unroll
            for (int mt = 0; mt < 2; mt++)
                #pragma unroll
                for (int n = 0; n < 8; n++)
                    mma_f16(o[mt][n], pa[mt][s], vfr[n][0], vfr[n][1]);
        }

        if (kt + 2 < KT) { loadKV(kt + 2); CPCOMMIT(); }
    }

    // finalize: normalize, split fp16 hi/lo, store
    #pragma unroll
    for (int mt = 0; mt < 2; mt++) {
        const float i0 = 1.f / lL[mt][0], i1 = 1.f / lL[mt][1];
        const int r0 = wrow + mt * 16 + gg;
        const int r1 = r0 + 8;
        #pragma unroll
        for (int n = 0; n < 8; n++) {
            const int col = h * 64 + n * 8 + tg * 2;
            float v0 = o[mt][n][0] * i0, v1 = o[mt][n][1] * i0;
            float v2 = o[mt][n][2] * i1, v3 = o[mt][n][3] * i1;
            __half2 h0 = __floats2half2_rn(v0, v1);
            __half2 h1 = __floats2half2_rn(v2, v3);
            __half2 e0 = __floats2half2_rn(v0 - __half2float(h0.x),
                                           v1 - __half2float(h0.y));
            __half2 e1 = __floats2half2_rn(v2 - __half2float(h1.x),
                                           v3 - __half2float(h1.y));
            *(uint32_t*)(ohi + (size_t)r0 * D_MODEL + col) = *(uint32_t*)&h0;
            *(uint32_t*)(olo + (size_t)r0 * D_MODEL + col) = *(uint32_t*)&e0;
            *(uint32_t*)(ohi + (size_t)r1 * D_MODEL + col) = *(uint32_t*)&h1;
            *(uint32_t*)(olo + (size_t)r1 * D_MODEL + col) = *(uint32_t*)&e1;
        }
    }
}

// ---------------------------------------------------------------------------
// Launch
// ---------------------------------------------------------------------------
extern "C" void kernel_launch(void* const* d_in, const int* in_sizes, int n_in,
                              void* d_out, int out_size)
{
    const float* queries = (const float*)d_in[0];
    const float* keys    = (const float*)d_in[1];
    const float* values  = (const float*)d_in[2];
    const float* Wq      = (const float*)d_in[3];
    const float* bq      = (const float*)d_in[4];
    const float* Wk      = (const float*)d_in[5];
    const float* bk      = (const float*)d_in[6];
    const float* Wv      = (const float*)d_in[7];
    const float* bv      = (const float*)d_in[8];
    const float* Wo      = (const float*)d_in[9];
    const float* bo      = (const float*)d_in[10];
    float*       out     = (float*)d_out;

    __half *qh, *kh, *vh;
    __half *ahi, *alo, *bhi, *blo, *chi, *clo;
    __half *wq, *wk, *wv, *wo;
    cudaGetSymbolAddress((void**)&qh,  g_qh);
    cudaGetSymbolAddress((void**)&kh,  g_kh);
    cudaGetSymbolAddress((void**)&vh,  g_vh);
    cudaGetSymbolAddress((void**)&ahi, g_ahi);
    cudaGetSymbolAddress((void**)&alo, g_alo);
    cudaGetSymbolAddress((void**)&bhi, g_bhi);
    cudaGetSymbolAddress((void**)&blo, g_blo);
    cudaGetSymbolAddress((void**)&chi, g_chi);
    cudaGetSymbolAddress((void**)&clo, g_clo);
    cudaGetSymbolAddress((void**)&wq,  g_wq);
    cudaGetSymbolAddress((void**)&wk,  g_wk);
    cudaGetSymbolAddress((void**)&wv,  g_wv);
    cudaGetSymbolAddress((void**)&wo,  g_wo);

    cudaFuncSetAttribute(gemm_qkv, cudaFuncAttributeMaxDynamicSharedMemorySize, 4 * GSTAGE);
    cudaFuncSetAttribute(gemm_o,   cudaFuncAttributeMaxDynamicSharedMemorySize, 4 * GSTAGE);

    // fused weight + activation prep
    prep<<<dim3(64, 64, 7), 256>>>(
        Wq, Wk, Wv, Wo,
        (const float4*)queries, (const float4*)keys, (const float4*)values,
        wq, wk, wv, wo,
        ahi, alo, bhi, blo, chi, clo);

    // Q + K + V projections fused
    gemm_qkv<<<dim3(24, S_LEN / 128), 128, 4 * GSTAGE>>>(
        ahi, alo, bhi, blo, chi, clo,
        wq, wk, wv, bq, bk, bv, qh, kh, vh);

    // causal GQA flash attention -> fp16 hi/lo split output
    flash<<<dim3(S_LEN / 128, H_Q), 128>>>(qh, kh, vh, ahi, alo);

    // output projection
    gemm_o<<<dim3(D_MODEL / 128, S_LEN / 128), 128, 4 * GSTAGE>>>(
        ahi, alo, wo, bo, out);
}

// round 11
// speedup vs baseline: 2.0268x; 1.5123x over previous
#include <cuda_runtime.h>
#include <cuda_bf16.h>
#include <cuda_fp16.h>
#include <cstdint>

// ===========================================================================
// GQA layer, sm_103 baseline-PTX path: mma.sync (HMMA) everywhere.
//   - projections: single-pass fp16 GEMM (A fp16, W fp16, fp32 accum),
//       CTA tile 128x128, BK=64, 4 warps (64x64), 3-stage cp.async, 2 CTA/SM
//   - attention:   fp16 FA-2, q-tile 128/CTA, 4 warps, 3-stage KV ring,
//       ex2.approx.f16x2 softmax + MMA row-sums, fp16 output
// ===========================================================================

#define S_LEN   2048
#define D_MODEL 2048
#define H_Q     32
#define KV_W    512
#define GK      2048
#define QSCALE  0.1803368801111244f   // 0.125 * log2(e)
#define ONES2   0x3C003C00u           // half2(1.0, 1.0)

// ------------------------------ scratch ------------------------------------
__device__ __align__(16) __half g_qh[S_LEN * D_MODEL];
__device__ __align__(16) __half g_kh[S_LEN * KV_W];
__device__ __align__(16) __half g_vh[S_LEN * KV_W];

// fp16 activations: A (queries / attn-out), B (keys), C (values)
__device__ __align__(16) __half g_ah[S_LEN * D_MODEL];
__device__ __align__(16) __half g_bh[S_LEN * D_MODEL];
__device__ __align__(16) __half g_ch[S_LEN * D_MODEL];

// transposed weights, fp16, [N][K]
__device__ __align__(16) __half g_wq[D_MODEL * GK];
__device__ __align__(16) __half g_wk[KV_W * GK];
__device__ __align__(16) __half g_wv[KV_W * GK];
__device__ __align__(16) __half g_wo[D_MODEL * GK];

// ------------------------------ helpers ------------------------------------
__device__ __forceinline__ uint32_t smem_u32(const void* p) {
    uint32_t a;
    asm("{ .reg .u64 t; cvta.to.shared.u64 t, %1; cvt.u32.u64 %0, t; }"
        : "=r"(a) : "l"(p));
    return a;
}

#define CP16(dst, src) \
    asm volatile("cp.async.cg.shared.global [%0], [%1], 16;" \
                 :: "r"(dst), "l"(src))
#define CPCOMMIT() asm volatile("cp.async.commit_group;" ::: "memory")
#define CPWAIT(n)  asm volatile("cp.async.wait_group %0;" :: "n"(n) : "memory")

__device__ __forceinline__ void ldsm_x4(uint32_t& r0, uint32_t& r1,
                                        uint32_t& r2, uint32_t& r3, uint32_t a) {
    asm volatile("ldmatrix.sync.aligned.m8n8.x4.shared.b16 {%0,%1,%2,%3}, [%4];"
                 : "=r"(r0), "=r"(r1), "=r"(r2), "=r"(r3) : "r"(a));
}
__device__ __forceinline__ void ldsm_x4t(uint32_t& r0, uint32_t& r1,
                                         uint32_t& r2, uint32_t& r3, uint32_t a) {
    asm volatile("ldmatrix.sync.aligned.m8n8.x4.trans.shared.b16 {%0,%1,%2,%3}, [%4];"
                 : "=r"(r0), "=r"(r1), "=r"(r2), "=r"(r3) : "r"(a));
}

__device__ __forceinline__ void mma_f16(float* c, const uint32_t* a,
                                        uint32_t b0, uint32_t b1) {
    asm volatile("mma.sync.aligned.m16n8k16.row.col.f32.f16.f16.f32 "
                 "{%0,%1,%2,%3}, {%4,%5,%6,%7}, {%8,%9}, {%0,%1,%2,%3};"
                 : "+f"(c[0]), "+f"(c[1]), "+f"(c[2]), "+f"(c[3])
                 : "r"(a[0]), "r"(a[1]), "r"(a[2]), "r"(a[3]), "r"(b0), "r"(b1));
}

__device__ __forceinline__ uint32_t h2exp2(uint32_t x) {
    uint32_t r;
    asm("ex2.approx.f16x2 %0, %1;" : "=r"(r) : "r"(x));
    return r;
}
__device__ __forceinline__ uint32_t packh2(float a, float b) {
    __half2 h = __floats2half2_rn(a, b);
    return *reinterpret_cast<uint32_t*>(&h);
}

// ---------------------------------------------------------------------------
// prep: fused weight transpose->fp16 (z 0..3) + activation->fp16 (z 4..6)
// grid (64, 64, 7), 256 threads
// ---------------------------------------------------------------------------
__global__ __launch_bounds__(256)
void prep(const float* __restrict__ Wq, const float* __restrict__ Wk,
          const float* __restrict__ Wv, const float* __restrict__ Wo,
          const float4* __restrict__ Qa, const float4* __restrict__ Ka,
          const float4* __restrict__ Va,
          __half* __restrict__ wq, __half* __restrict__ wk,
          __half* __restrict__ wv, __half* __restrict__ wo,
          __half* __restrict__ ah, __half* __restrict__ bh,
          __half* __restrict__ ch)
{
    __shared__ float tile[32][33];
    const int z = blockIdx.z;
    if (z < 4) {
        const float* W;  __half* dst;  int Ncols;
        if      (z == 0) { W = Wq; dst = wq; Ncols = D_MODEL; }
        else if (z == 1) { W = Wk; dst = wk; Ncols = KV_W; }
        else if (z == 2) { W = Wv; dst = wv; Ncols = KV_W; }
        else             { W = Wo; dst = wo; Ncols = D_MODEL; }

        const int bx = blockIdx.x, by = blockIdx.y;
        if (bx * 32 >= Ncols) return;
        const int tx = threadIdx.x & 31, ty = threadIdx.x >> 5;

        #pragma unroll
        for (int i = 0; i < 32; i += 8)
            tile[ty + i][tx] = W[(size_t)(by * 32 + ty + i) * Ncols + bx * 32 + tx];
        __syncthreads();
        #pragma unroll
        for (int i = 0; i < 32; i += 8) {
            const int n = bx * 32 + ty + i;
            const int k = by * 32 + tx;
            dst[(size_t)n * GK + k] = __float2half_rn(tile[tx][ty + i]);
        }
    } else {
        const float4* A;  __half* dst;
        if      (z == 4) { A = Qa; dst = ah; }
        else if (z == 5) { A = Ka; dst = bh; }
        else             { A = Va; dst = ch; }

        const int i = (blockIdx.y * 64 + blockIdx.x) * 256 + threadIdx.x;
        float4 v = A[i];
        __half2 h0 = __floats2half2_rn(v.x, v.y);
        __half2 h1 = __floats2half2_rn(v.z, v.w);
        uint2 u = make_uint2(*(uint32_t*)&h0, *(uint32_t*)&h1);
        *(uint2*)(dst + (size_t)i * 4) = u;
    }
}

// ---------------------------------------------------------------------------
// GEMM body: C[128x128] = A @ B^T + bias, single-pass fp16.
// BK=64, 128 thr, 4 warps (2m x 2n), warp tile 64x64.
// Stage: A(16K) + B(16K) = 32KB; 3 stages = 96KB -> 2 CTAs/SM.
// Rows are 128B (64 halves): swizzle (c ^ (r&7)) like the flash tiles.
// MODE 0: float out; MODE 1: half out; MODE 2: half out * QSCALE.
// ---------------------------------------------------------------------------
#define GSTAGE 32768

template <int MODE>
__device__ __forceinline__
void gemm_body(const __half* __restrict__ A, const __half* __restrict__ B,
               const float* __restrict__ bias, void* __restrict__ Cout,
               int Ntot, int m0, int n0, uint32_t sb)
{
    const int tid  = threadIdx.x;
    const int lane = tid & 31;
    const int wid  = tid >> 5;
    const int wm   = (wid & 1) * 64;
    const int wn   = (wid >> 1) * 64;
    const int gg   = lane >> 2, tg = lane & 3;
    const int mi   = lane >> 3;

    float acc[4][8][4];
    #pragma unroll
    for (int a = 0; a < 4; a++)
        #pragma unroll
        for (int b = 0; b < 8; b++)
            #pragma unroll
            for (int c = 0; c < 4; c++) acc[a][b][c] = 0.f;

    auto load_stage = [&](int it) {
        const uint32_t st = sb + (it % 3) * GSTAGE;
        const int k0 = it * 64;
        #pragma unroll
        for (int t = 0; t < 8; t++) {
            const int f   = tid + t * 128;        // 0..1023
            const int row = f >> 3, c = f & 7;
            const uint32_t sw = row * 128 + ((c ^ (row & 7)) * 16);
            CP16(st + sw,         A + (size_t)(m0 + row) * GK + k0 + c * 8);
            CP16(st + 16384 + sw, B + (size_t)(n0 + row) * GK + k0 + c * 8);
        }
    };

    load_stage(0); CPCOMMIT();
    load_stage(1); CPCOMMIT();

    const int NIT = GK / 64;
    for (int it = 0; it < NIT; it++) {
        if (it + 1 < NIT) { CPWAIT(1); } else { CPWAIT(0); }
        __syncthreads();
        const uint32_t st = sb + (it % 3) * GSTAGE;

        #pragma unroll
        for (int s = 0; s < 4; s++) {
            uint32_t aF[4][4];
            #pragma unroll
            for (int mt = 0; mt < 4; mt++) {
                const int r = wm + mt * 16 + (mi & 1) * 8 + (lane & 7);
                const int c = 2 * s + (mi >> 1);
                ldsm_x4(aF[mt][0], aF[mt][1], aF[mt][2], aF[mt][3],
                        st + r * 128 + ((c ^ (r & 7)) * 16));
            }
            uint32_t bF[8][2];
            #pragma unroll
            for (int nt = 0; nt < 4; nt++) {
                const int r = wn + nt * 16 + (mi >> 1) * 8 + (lane & 7);
                const int c = 2 * s + (mi & 1);
                ldsm_x4(bF[2*nt][0], bF[2*nt][1], bF[2*nt+1][0], bF[2*nt+1][1],
                        st + 16384 + r * 128 + ((c ^ (r & 7)) * 16));
            }
            #pragma unroll
            for (int mt = 0; mt < 4; mt++)
                #pragma unroll
                for (int n = 0; n < 8; n++)
                    mma_f16(acc[mt][n], aF[mt], bF[n][0], bF[n][1]);
        }
        if (it + 2 < NIT) { load_stage(it + 2); CPCOMMIT(); }
    }

    #pragma unroll
    for (int mt = 0; mt < 4; mt++)
        #pragma unroll
        for (int n = 0; n < 8; n++) {
            const int r0  = m0 + wm + mt * 16 + gg;
            const int col = n0 + wn + n * 8 + tg * 2;
            const float b0 = bias[col], b1 = bias[col + 1];
            if (MODE == 0) {
                float* C = (float*)Cout;
                *(float2*)(C + (size_t)r0 * Ntot + col) =
                    make_float2(acc[mt][n][0] + b0, acc[mt][n][1] + b1);
                *(float2*)(C + (size_t)(r0 + 8) * Ntot + col) =
                    make_float2(acc[mt][n][2] + b0, acc[mt][n][3] + b1);
            } else {
                const float sc = (MODE == 2) ? QSCALE : 1.0f;
                __half* C = (__half*)Cout;
                __half2 h0 = __floats2half2_rn((acc[mt][n][0] + b0) * sc,
                                               (acc[mt][n][1] + b1) * sc);
                __half2 h1 = __floats2half2_rn((acc[mt][n][2] + b0) * sc,
                                               (acc[mt][n][3] + b1) * sc);
                *(__half2*)(C + (size_t)r0 * Ntot + col) = h0;
                *(__half2*)(C + (size_t)(r0 + 8) * Ntot + col) = h1;
            }
        }
}

__global__ __launch_bounds__(128, 2)
void gemm_qkv(const __half* __restrict__ Qa, const __half* __restrict__ Ka,
              const __half* __restrict__ Va,
              const __half* __restrict__ WQ, const __half* __restrict__ WK,
              const __half* __restrict__ WV,
              const float* __restrict__ bq, const float* __restrict__ bk,
              const float* __restrict__ bv,
              __half* __restrict__ qh, __half* __restrict__ kh, __half* __restrict__ vh)
{
    extern __shared__ char sm[];
    const uint32_t sb = smem_u32(sm);
    const int bx = blockIdx.x;
    const int m0 = blockIdx.y * 128;
    if (bx < 16)
        gemm_body<2>(Qa, WQ, bq, qh, D_MODEL, m0, bx * 128, sb);
    else if (bx < 20)
        gemm_body<1>(Ka, WK, bk, kh, KV_W, m0, (bx - 16) * 128, sb);
    else
        gemm_body<1>(Va, WV, bv, vh, KV_W, m0, (bx - 20) * 128, sb);
}

__global__ __launch_bounds__(128, 2)
void gemm_o(const __half* __restrict__ A, const __half* __restrict__ B,
            const float* __restrict__ bias, float* __restrict__ Cout)
{
    extern __shared__ char sm[];
    gemm_body<0>(A, B, bias, Cout, D_MODEL,
                 blockIdx.y * 128, blockIdx.x * 128, smem_u32(sm));
}

// ---------------------------------------------------------------------------
// fp16 HMMA causal flash attention.  q-tile 128/CTA, 4 warps (32 q-rows each),
// kv tile 64, 3-stage ring, ONE sync/iter.  ex2.approx.f16x2 softmax,
// MMA row-sums, s=0 V-fragment hoist.  Output single fp16.
// ---------------------------------------------------------------------------
__global__ __launch_bounds__(128)
void flash(const __half* __restrict__ qbuf, const __half* __restrict__ kbuf,
           const __half* __restrict__ vbuf, __half* __restrict__ obuf)
{
    __shared__ __align__(16) __half sQ[128 * 64];
    __shared__ __align__(16) __half sK[3][64 * 64];
    __shared__ __align__(16) __half sV[3][64 * 64];

    const int qt   = (int)gridDim.x - 1 - (int)blockIdx.x;
    const int h    = blockIdx.y;
    const int g    = h >> 2;
    const int tid  = threadIdx.x;
    const int warp = tid >> 5, lane = tid & 31;
    const int gg   = lane >> 2, tg = lane & 3;
    const int mi   = lane >> 3;
    const int q0   = qt * 128;
    const int wrow = q0 + warp * 32;

    const uint32_t qb  = smem_u32(sQ);
    const uint32_t kb0 = smem_u32(sK);
    const uint32_t vb0 = smem_u32(sV);

    #pragma unroll
    for (int i = 0; i < 8; i++) {
        const int f = tid + i * 128;
        const int r = f >> 3, c = f & 7;
        CP16(qb + r * 128 + ((c ^ (r & 7)) * 16),
             qbuf + (size_t)(q0 + r) * D_MODEL + h * 64 + c * 8);
    }
    auto loadKV = [&](int kt) {
        const uint32_t ko = kb0 + (kt % 3) * 8192;
        const uint32_t vo = vb0 + (kt % 3) * 8192;
        #pragma unroll
        for (int i = 0; i < 4; i++) {
            const int f = tid + i * 128;
            const int r = f >> 3, c = f & 7;
            const size_t src = (size_t)(kt * 64 + r) * KV_W + g * 64 + c * 8;
            const uint32_t d = r * 128 + ((c ^ (r & 7)) * 16);
            CP16(ko + d, kbuf + src);
            CP16(vo + d, vbuf + src);
        }
    };
    const int KT = 2 * qt + 2;
    loadKV(0); CPCOMMIT();
    if (KT > 1) loadKV(1);
    CPCOMMIT();
    CPWAIT(1);
    __syncthreads();

    uint32_t qa[4][2][4];
    #pragma unroll
    for (int mt = 0; mt < 2; mt++) {
        const int r = warp * 32 + mt * 16 + (mi & 1) * 8 + (lane & 7);
        #pragma unroll
        for (int s = 0; s < 4; s++) {
            const int c = 2 * s + (mi >> 1);
            ldsm_x4(qa[s][mt][0], qa[s][mt][1], qa[s][mt][2], qa[s][mt][3],
                    qb + r * 128 + ((c ^ (r & 7)) * 16));
        }
    }

    float o[2][8][4];
    #pragma unroll
    for (int mt = 0; mt < 2; mt++)
        #pragma unroll
        for (int n = 0; n < 8; n++)
            #pragma unroll
            for (int c = 0; c < 4; c++) o[mt][n][c] = 0.f;
    float mM[2][2] = {{-1e30f, -1e30f}, {-1e30f, -1e30f}};
    float lL[2][2] = {{0.f, 0.f}, {0.f, 0.f}};

    for (int kt = 0; kt < KT; kt++) {
        if (kt > 0) {
            if (kt + 1 < KT) { CPWAIT(1); } else { CPWAIT(0); }
            __syncthreads();
        }
        const uint32_t ko = kb0 + (kt % 3) * 8192;
        const uint32_t vo = vb0 + (kt % 3) * 8192;

        float sc[2][8][4];
        #pragma unroll
        for (int mt = 0; mt < 2; mt++)
            #pragma unroll
            for (int n = 0; n < 8; n++)
                #pragma unroll
                for (int c = 0; c < 4; c++) sc[mt][n][c] = 0.f;

        #pragma unroll
        for (int s = 0; s < 4; s++) {
            uint32_t bfr[8][2];
            #pragma unroll
            for (int nt = 0; nt < 4; nt++) {
                const int r = nt * 16 + (mi >> 1) * 8 + (lane & 7);
                const int c = 2 * s + (mi & 1);
                ldsm_x4(bfr[2*nt][0], bfr[2*nt][1], bfr[2*nt+1][0], bfr[2*nt+1][1],
                        ko + r * 128 + ((c ^ (r & 7)) * 16));
            }
            #pragma unroll
            for (int mt = 0; mt < 2; mt++)
                #pragma unroll
                for (int n = 0; n < 8; n++)
                    mma_f16(sc[mt][n], qa[s][mt], bfr[n][0], bfr[n][1]);
        }

        uint32_t vf0[8][2];
        #pragma unroll
        for (int nt = 0; nt < 4; nt++) {
            const int r = (mi & 1) * 8 + (lane & 7);
            const int c = 2 * nt + (mi >> 1);
            ldsm_x4t(vf0[2*nt][0], vf0[2*nt][1], vf0[2*nt+1][0], vf0[2*nt+1][1],
                     vo + r * 128 + ((c ^ (r & 7)) * 16));
        }

        if (kt * 64 + 63 > wrow) {
            #pragma unroll
            for (int mt = 0; mt < 2; mt++) {
                const int r0 = wrow + mt * 16 + gg;
                const int r1 = r0 + 8;
                #pragma unroll
                for (int n = 0; n < 8; n++) {
                    const int col = kt * 64 + n * 8 + tg * 2;
                    if (col     > r0) sc[mt][n][0] = -1e30f;
                    if (col + 1 > r0) sc[mt][n][1] = -1e30f;
                    if (col     > r1) sc[mt][n][2] = -1e30f;
                    if (col + 1 > r1) sc[mt][n][3] = -1e30f;
                }
            }
        }

        uint32_t pa[2][4][4];
        #pragma unroll
        for (int mt = 0; mt < 2; mt++) {
            float mx0 = -1e30f, mx1 = -1e30f;
            #pragma unroll
            for (int n = 0; n < 8; n++) {
                mx0 = fmaxf(mx0, fmaxf(sc[mt][n][0], sc[mt][n][1]));
                mx1 = fmaxf(mx1, fmaxf(sc[mt][n][2], sc[mt][n][3]));
            }
            mx0 = fmaxf(mx0, __shfl_xor_sync(0xffffffffu, mx0, 1));
            mx0 = fmaxf(mx0, __shfl_xor_sync(0xffffffffu, mx0, 2));
            mx1 = fmaxf(mx1, __shfl_xor_sync(0xffffffffu, mx1, 1));
            mx1 = fmaxf(mx1, __shfl_xor_sync(0xffffffffu, mx1, 2));
            const float mn0 = fmaxf(mM[mt][0], mx0);
            const float mn1 = fmaxf(mM[mt][1], mx1);
            const float c0 = exp2f(mM[mt][0] - mn0);
            const float c1 = exp2f(mM[mt][1] - mn1);
            mM[mt][0] = mn0; mM[mt][1] = mn1;

            #pragma unroll
            for (int s = 0; s < 4; s++) {
                pa[mt][s][0] = h2exp2(packh2(sc[mt][2*s][0]   - mn0, sc[mt][2*s][1]   - mn0));
                pa[mt][s][1] = h2exp2(packh2(sc[mt][2*s][2]   - mn1, sc[mt][2*s][3]   - mn1));
                pa[mt][s][2] = h2exp2(packh2(sc[mt][2*s+1][0] - mn0, sc[mt][2*s+1][1] - mn0));
                pa[mt][s][3] = h2exp2(packh2(sc[mt][2*s+1][2] - mn1, sc[mt][2*s+1][3] - mn1));
            }

            float lacc[4] = {0.f, 0.f, 0.f, 0.f};
            #pragma unroll
            for (int s = 0; s < 4; s++)
                mma_f16(lacc, pa[mt][s], ONES2, ONES2);
            lL[mt][0] = lL[mt][0] * c0 + lacc[0];
            lL[mt][1] = lL[mt][1] * c1 + lacc[2];

            #pragma unroll
            for (int n = 0; n < 8; n++) {
                o[mt][n][0] *= c0; o[mt][n][1] *= c0;
                o[mt][n][2] *= c1; o[mt][n][3] *= c1;
            }
        }

        #pragma unroll
        for (int mt = 0; mt < 2; mt++)
            #pragma unroll
            for (int n = 0; n < 8; n++)
                mma_f16(o[mt][n], pa[mt][0], vf0[n][0], vf0[n][1]);

        #pragma unroll
        for (int s = 1; s < 4; s++) {
            uint32_t vfr[8][2];
            #pragma unroll
            for (int nt = 0; nt < 4; nt++) {
                const int r = s * 16 + (mi & 1) * 8 + (lane & 7);
                const int c = 2 * nt + (mi >> 1);
                ldsm_x4t(vfr[2*nt][0], vfr[2*nt][1], vfr[2*nt+1][0], vfr[2*nt+1][1],
                         vo + r * 128 + ((c ^ (r & 7)) * 16));
            }
            #pragma unroll
            for (int mt = 0; mt < 2; mt++)
                #pragma unroll
                for (int n = 0; n < 8; n++)
                    mma_f16(o[mt][n], pa[mt][s], vfr[n][0], vfr[n][1]);
        }

        if (kt + 2 < KT) { loadKV(kt + 2); CPCOMMIT(); }
    }

    // finalize: normalize, store fp16
    #pragma unroll
    for (int mt = 0; mt < 2; mt++) {
        const float i0 = 1.f / lL[mt][0], i1 = 1.f / lL[mt][1];
        const int r0 = wrow + mt * 16 + gg;
        const int r1 = r0 + 8;
        #pragma unroll
        for (int n = 0; n < 8; n++) {
            const int col = h * 64 + n * 8 + tg * 2;
            *(uint32_t*)(obuf + (size_t)r0 * D_MODEL + col) =
                packh2(o[mt][n][0] * i0, o[mt][n][1] * i0);
            *(uint32_t*)(obuf + (size_t)r1 * D_MODEL + col) =
                packh2(o[mt][n][2] * i1, o[mt][n][3] * i1);
        }
    }
}

// ---------------------------------------------------------------------------
// Launch
// ---------------------------------------------------------------------------
extern "C" void kernel_launch(void* const* d_in, const int* in_sizes, int n_in,
                              void* d_out, int out_size)
{
    const float* queries = (const float*)d_in[0];
    const float* keys    = (const float*)d_in[1];
    const float* values  = (const float*)d_in[2];
    const float* Wq      = (const float*)d_in[3];
    const float* bq      = (const float*)d_in[4];
    const float* Wk      = (const float*)d_in[5];
    const float* bk      = (const float*)d_in[6];
    const float* Wv      = (const float*)d_in[7];
    const float* bv      = (const float*)d_in[8];
    const float* Wo      = (const float*)d_in[9];
    const float* bo      = (const float*)d_in[10];
    float*       out     = (float*)d_out;

    __half *qh, *kh, *vh, *ah, *bh, *ch, *wq, *wk, *wv, *wo;
    cudaGetSymbolAddress((void**)&qh, g_qh);
    cudaGetSymbolAddress((void**)&kh, g_kh);
    cudaGetSymbolAddress((void**)&vh, g_vh);
    cudaGetSymbolAddress((void**)&ah, g_ah);
    cudaGetSymbolAddress((void**)&bh, g_bh);
    cudaGetSymbolAddress((void**)&ch, g_ch);
    cudaGetSymbolAddress((void**)&wq, g_wq);
    cudaGetSymbolAddress((void**)&wk, g_wk);
    cudaGetSymbolAddress((void**)&wv, g_wv);
    cudaGetSymbolAddress((void**)&wo, g_wo);

    cudaFuncSetAttribute(gemm_qkv, cudaFuncAttributeMaxDynamicSharedMemorySize, 3 * GSTAGE);
    cudaFuncSetAttribute(gemm_o,   cudaFuncAttributeMaxDynamicSharedMemorySize, 3 * GSTAGE);

    // fused weight + activation prep
    prep<<<dim3(64, 64, 7), 256>>>(
        Wq, Wk, Wv, Wo,
        (const float4*)queries, (const float4*)keys, (const float4*)values,
        wq, wk, wv, wo, ah, bh, ch);

    // Q + K + V projections fused
    gemm_qkv<<<dim3(24, S_LEN / 128), 128, 3 * GSTAGE>>>(
        ah, bh, ch, wq, wk, wv, bq, bk, bv, qh, kh, vh);

    // causal GQA flash attention -> fp16 output (reuses g_ah)
    flash<<<dim3(S_LEN / 128, H_Q), 128>>>(qh, kh, vh, ah);

    // output projection
    gemm_o<<<dim3(D_MODEL / 128, S_LEN / 128), 128, 3 * GSTAGE>>>(
        ah, wo, bo, out);
}

// round 12
// speedup vs baseline: 2.2731x; 1.1215x over previous
#include <cuda_runtime.h>
#include <cuda_bf16.h>
#include <cuda_fp16.h>
#include <cstdint>

// ===========================================================================
// GQA layer, sm_103 baseline-PTX path: mma.sync (HMMA) everywhere.
//   - projections: single-pass fp16 GEMM (A fp16, W fp16, fp32 accum)
//   - flash attention + O-projection FUSED in one launch; gemm_o tiles
//     spin on per-qt completion counters filled by flash CTAs.
// ===========================================================================

#define S_LEN   2048
#define D_MODEL 2048
#define H_Q     32
#define KV_W    512
#define GK      2048
#define QSCALE  0.1803368801111244f   // 0.125 * log2(e)
#define ONES2   0x3C003C00u           // half2(1.0, 1.0)

// ------------------------------ scratch ------------------------------------
__device__ __align__(16) __half g_qh[S_LEN * D_MODEL];
__device__ __align__(16) __half g_kh[S_LEN * KV_W];
__device__ __align__(16) __half g_vh[S_LEN * KV_W];

__device__ __align__(16) __half g_ah[S_LEN * D_MODEL];
__device__ __align__(16) __half g_bh[S_LEN * D_MODEL];
__device__ __align__(16) __half g_ch[S_LEN * D_MODEL];

__device__ __align__(16) __half g_wq[D_MODEL * GK];
__device__ __align__(16) __half g_wk[KV_W * GK];
__device__ __align__(16) __half g_wv[KV_W * GK];
__device__ __align__(16) __half g_wo[D_MODEL * GK];

__device__ int g_cnt[16];   // per-qt flash completion counters

// ------------------------------ helpers ------------------------------------
__device__ __forceinline__ uint32_t smem_u32(const void* p) {
    uint32_t a;
    asm("{ .reg .u64 t; cvta.to.shared.u64 t, %1; cvt.u32.u64 %0, t; }"
        : "=r"(a) : "l"(p));
    return a;
}

#define CP16(dst, src) \
    asm volatile("cp.async.cg.shared.global [%0], [%1], 16;" \
                 :: "r"(dst), "l"(src))
#define CPCOMMIT() asm volatile("cp.async.commit_group;" ::: "memory")
#define CPWAIT(n)  asm volatile("cp.async.wait_group %0;" :: "n"(n) : "memory")

__device__ __forceinline__ void ldsm_x4(uint32_t& r0, uint32_t& r1,
                                        uint32_t& r2, uint32_t& r3, uint32_t a) {
    asm volatile("ldmatrix.sync.aligned.m8n8.x4.shared.b16 {%0,%1,%2,%3}, [%4];"
                 : "=r"(r0), "=r"(r1), "=r"(r2), "=r"(r3) : "r"(a));
}
__device__ __forceinline__ void ldsm_x4t(uint32_t& r0, uint32_t& r1,
                                         uint32_t& r2, uint32_t& r3, uint32_t a) {
    asm volatile("ldmatrix.sync.aligned.m8n8.x4.trans.shared.b16 {%0,%1,%2,%3}, [%4];"
                 : "=r"(r0), "=r"(r1), "=r"(r2), "=r"(r3) : "r"(a));
}

__device__ __forceinline__ void mma_f16(float* c, const uint32_t* a,
                                        uint32_t b0, uint32_t b1) {
    asm volatile("mma.sync.aligned.m16n8k16.row.col.f32.f16.f16.f32 "
                 "{%0,%1,%2,%3}, {%4,%5,%6,%7}, {%8,%9}, {%0,%1,%2,%3};"
                 : "+f"(c[0]), "+f"(c[1]), "+f"(c[2]), "+f"(c[3])
                 : "r"(a[0]), "r"(a[1]), "r"(a[2]), "r"(a[3]), "r"(b0), "r"(b1));
}

__device__ __forceinline__ uint32_t h2exp2(uint32_t x) {
    uint32_t r;
    asm("ex2.approx.f16x2 %0, %1;" : "=r"(r) : "r"(x));
    return r;
}
__device__ __forceinline__ uint32_t packh2(float a, float b) {
    __half2 h = __floats2half2_rn(a, b);
    return *reinterpret_cast<uint32_t*>(&h);
}

// ---------------------------------------------------------------------------
// prep: weight transpose->fp16 (z 0..3) + activation->fp16 (z 4..6)
// also zeroes the flash->gemm_o counters.
// ---------------------------------------------------------------------------
__global__ __launch_bounds__(256)
void prep(const float* __restrict__ Wq, const float* __restrict__ Wk,
          const float* __restrict__ Wv, const float* __restrict__ Wo,
          const float4* __restrict__ Qa, const float4* __restrict__ Ka,
          const float4* __restrict__ Va,
          __half* __restrict__ wq, __half* __restrict__ wk,
          __half* __restrict__ wv, __half* __restrict__ wo,
          __half* __restrict__ ah, __half* __restrict__ bh,
          __half* __restrict__ ch)
{
    if (blockIdx.x == 0 && blockIdx.y == 0 && blockIdx.z == 0 &&
        threadIdx.x < 16)
        g_cnt[threadIdx.x] = 0;

    __shared__ float tile[32][33];
    const int z = blockIdx.z;
    if (z < 4) {
        const float* W;  __half* dst;  int Ncols;
        if      (z == 0) { W = Wq; dst = wq; Ncols = D_MODEL; }
        else if (z == 1) { W = Wk; dst = wk; Ncols = KV_W; }
        else if (z == 2) { W = Wv; dst = wv; Ncols = KV_W; }
        else             { W = Wo; dst = wo; Ncols = D_MODEL; }

        const int bx = blockIdx.x, by = blockIdx.y;
        if (bx * 32 >= Ncols) return;
        const int tx = threadIdx.x & 31, ty = threadIdx.x >> 5;

        #pragma unroll
        for (int i = 0; i < 32; i += 8)
            tile[ty + i][tx] = W[(size_t)(by * 32 + ty + i) * Ncols + bx * 32 + tx];
        __syncthreads();
        #pragma unroll
        for (int i = 0; i < 32; i += 8) {
            const int n = bx * 32 + ty + i;
            const int k = by * 32 + tx;
            dst[(size_t)n * GK + k] = __float2half_rn(tile[tx][ty + i]);
        }
    } else {
        const float4* A;  __half* dst;
        if      (z == 4) { A = Qa; dst = ah; }
        else if (z == 5) { A = Ka; dst = bh; }
        else             { A = Va; dst = ch; }

        const int i = (blockIdx.y * 64 + blockIdx.x) * 256 + threadIdx.x;
        float4 v = A[i];
        __half2 h0 = __floats2half2_rn(v.x, v.y);
        __half2 h1 = __floats2half2_rn(v.z, v.w);
        uint2 u = make_uint2(*(uint32_t*)&h0, *(uint32_t*)&h1);
        *(uint2*)(dst + (size_t)i * 4) = u;
    }
}

// ---------------------------------------------------------------------------
// GEMM body: C[128x128] = A @ B^T + bias, single-pass fp16, BK=64,
// 128 thr, 4 warps (2m x 2n), warp tile 64x64.  3-stage, 32KB/stage.
// MODE 0: float out; MODE 1: half out; MODE 2: half out * QSCALE.
// ---------------------------------------------------------------------------
#define GSTAGE 32768

template <int MODE>
__device__ __forceinline__
void gemm_body(const __half* __restrict__ A, const __half* __restrict__ B,
               const float* __restrict__ bias, void* __restrict__ Cout,
               int Ntot, int m0, int n0, uint32_t sb)
{
    const int tid  = threadIdx.x;
    const int lane = tid & 31;
    const int wid  = tid >> 5;
    const int wm   = (wid & 1) * 64;
    const int wn   = (wid >> 1) * 64;
    const int gg   = lane >> 2, tg = lane & 3;
    const int mi   = lane >> 3;

    float acc[4][8][4];
    #pragma unroll
    for (int a = 0; a < 4; a++)
        #pragma unroll
        for (int b = 0; b < 8; b++)
            #pragma unroll
            for (int c = 0; c < 4; c++) acc[a][b][c] = 0.f;

    auto load_stage = [&](int it) {
        const uint32_t st = sb + (it % 3) * GSTAGE;
        const int k0 = it * 64;
        #pragma unroll
        for (int t = 0; t < 8; t++) {
            const int f   = tid + t * 128;
            const int row = f >> 3, c = f & 7;
            const uint32_t sw = row * 128 + ((c ^ (row & 7)) * 16);
            CP16(st + sw,         A + (size_t)(m0 + row) * GK + k0 + c * 8);
            CP16(st + 16384 + sw, B + (size_t)(n0 + row) * GK + k0 + c * 8);
        }
    };

    load_stage(0); CPCOMMIT();
    load_stage(1); CPCOMMIT();

    const int NIT = GK / 64;
    for (int it = 0; it < NIT; it++) {
        if (it + 1 < NIT) { CPWAIT(1); } else { CPWAIT(0); }
        __syncthreads();
        const uint32_t st = sb + (it % 3) * GSTAGE;

        #pragma unroll
        for (int s = 0; s < 4; s++) {
            uint32_t aF[4][4];
            #pragma unroll
            for (int mt = 0; mt < 4; mt++) {
                const int r = wm + mt * 16 + (mi & 1) * 8 + (lane & 7);
                const int c = 2 * s + (mi >> 1);
                ldsm_x4(aF[mt][0], aF[mt][1], aF[mt][2], aF[mt][3],
                        st + r * 128 + ((c ^ (r & 7)) * 16));
            }
            uint32_t bF[8][2];
            #pragma unroll
            for (int nt = 0; nt < 4; nt++) {
                const int r = wn + nt * 16 + (mi >> 1) * 8 + (lane & 7);
                const int c = 2 * s + (mi & 1);
                ldsm_x4(bF[2*nt][0], bF[2*nt][1], bF[2*nt+1][0], bF[2*nt+1][1],
                        st + 16384 + r * 128 + ((c ^ (r & 7)) * 16));
            }
            #pragma unroll
            for (int mt = 0; mt < 4; mt++)
                #pragma unroll
                for (int n = 0; n < 8; n++)
                    mma_f16(acc[mt][n], aF[mt], bF[n][0], bF[n][1]);
        }
        if (it + 2 < NIT) { load_stage(it + 2); CPCOMMIT(); }
    }

    #pragma unroll
    for (int mt = 0; mt < 4; mt++)
        #pragma unroll
        for (int n = 0; n < 8; n++) {
            const int r0  = m0 + wm + mt * 16 + gg;
            const int col = n0 + wn + n * 8 + tg * 2;
            const float b0 = bias[col], b1 = bias[col + 1];
            if (MODE == 0) {
                float* C = (float*)Cout;
                *(float2*)(C + (size_t)r0 * Ntot + col) =
                    make_float2(acc[mt][n][0] + b0, acc[mt][n][1] + b1);
                *(float2*)(C + (size_t)(r0 + 8) * Ntot + col) =
                    make_float2(acc[mt][n][2] + b0, acc[mt][n][3] + b1);
            } else {
                const float sc = (MODE == 2) ? QSCALE : 1.0f;
                __half* C = (__half*)Cout;
                __half2 h0 = __floats2half2_rn((acc[mt][n][0] + b0) * sc,
                                               (acc[mt][n][1] + b1) * sc);
                __half2 h1 = __floats2half2_rn((acc[mt][n][2] + b0) * sc,
                                               (acc[mt][n][3] + b1) * sc);
                *(__half2*)(C + (size_t)r0 * Ntot + col) = h0;
                *(__half2*)(C + (size_t)(r0 + 8) * Ntot + col) = h1;
            }
        }
}

__global__ __launch_bounds__(128, 2)
void gemm_qkv(const __half* __restrict__ Qa, const __half* __restrict__ Ka,
              const __half* __restrict__ Va,
              const __half* __restrict__ WQ, const __half* __restrict__ WK,
              const __half* __restrict__ WV,
              const float* __restrict__ bq, const float* __restrict__ bk,
              const float* __restrict__ bv,
              __half* __restrict__ qh, __half* __restrict__ kh, __half* __restrict__ vh)
{
    extern __shared__ char sm[];
    const uint32_t sb = smem_u32(sm);
    const int bx = blockIdx.x;
    const int m0 = blockIdx.y * 128;
    if (bx < 16)
        gemm_body<2>(Qa, WQ, bq, qh, D_MODEL, m0, bx * 128, sb);
    else if (bx < 20)
        gemm_body<1>(Ka, WK, bk, kh, KV_W, m0, (bx - 16) * 128, sb);
    else
        gemm_body<1>(Va, WV, bv, vh, KV_W, m0, (bx - 20) * 128, sb);
}

// ---------------------------------------------------------------------------
// flash body (identical math to R11), parameterized on smem base + (qt, h)
// ---------------------------------------------------------------------------
__device__ __forceinline__
void flash_body(const __half* __restrict__ qbuf, const __half* __restrict__ kbuf,
                const __half* __restrict__ vbuf, __half* __restrict__ obuf,
                int qt, int h, char* smem)
{
    const uint32_t qb  = smem_u32(smem);            // 16 KB
    const uint32_t kb0 = qb + 16384;                // 3 x 8 KB
    const uint32_t vb0 = qb + 40960;                // 3 x 8 KB

    const int g    = h >> 2;
    const int tid  = threadIdx.x;
    const int warp = tid >> 5, lane = tid & 31;
    const int gg   = lane >> 2, tg = lane & 3;
    const int mi   = lane >> 3;
    const int q0   = qt * 128;
    const int wrow = q0 + warp * 32;

    #pragma unroll
    for (int i = 0; i < 8; i++) {
        const int f = tid + i * 128;
        const int r = f >> 3, c = f & 7;
        CP16(qb + r * 128 + ((c ^ (r & 7)) * 16),
             qbuf + (size_t)(q0 + r) * D_MODEL + h * 64 + c * 8);
    }
    auto loadKV = [&](int kt) {
        const uint32_t ko = kb0 + (kt % 3) * 8192;
        const uint32_t vo = vb0 + (kt % 3) * 8192;
        #pragma unroll
        for (int i = 0; i < 4; i++) {
            const int f = tid + i * 128;
            const int r = f >> 3, c = f & 7;
            const size_t src = (size_t)(kt * 64 + r) * KV_W + g * 64 + c * 8;
            const uint32_t d = r * 128 + ((c ^ (r & 7)) * 16);
            CP16(ko + d, kbuf + src);
            CP16(vo + d, vbuf + src);
        }
    };
    const int KT = 2 * qt + 2;
    loadKV(0); CPCOMMIT();
    if (KT > 1) loadKV(1);
    CPCOMMIT();
    CPWAIT(1);
    __syncthreads();

    uint32_t qa[4][2][4];
    #pragma unroll
    for (int mt = 0; mt < 2; mt++) {
        const int r = warp * 32 + mt * 16 + (mi & 1) * 8 + (lane & 7);
        #pragma unroll
        for (int s = 0; s < 4; s++) {
            const int c = 2 * s + (mi >> 1);
            ldsm_x4(qa[s][mt][0], qa[s][mt][1], qa[s][mt][2], qa[s][mt][3],
                    qb + r * 128 + ((c ^ (r & 7)) * 16));
        }
    }

    float o[2][8][4];
    #pragma unroll
    for (int mt = 0; mt < 2; mt++)
        #pragma unroll
        for (int n = 0; n < 8; n++)
            #pragma unroll
            for (int c = 0; c < 4; c++) o[mt][n][c] = 0.f;
    float mM[2][2] = {{-1e30f, -1e30f}, {-1e30f, -1e30f}};
    float lL[2][2] = {{0.f, 0.f}, {0.f, 0.f}};

    for (int kt = 0; kt < KT; kt++) {
        if (kt > 0) {
            if (kt + 1 < KT) { CPWAIT(1); } else { CPWAIT(0); }
            __syncthreads();
        }
        const uint32_t ko = kb0 + (kt % 3) * 8192;
        const uint32_t vo = vb0 + (kt % 3) * 8192;

        float sc[2][8][4];
        #pragma unroll
        for (int mt = 0; mt < 2; mt++)
            #pragma unroll
            for (int n = 0; n < 8; n++)
                #pragma unroll
                for (int c = 0; c < 4; c++) sc[mt][n][c] = 0.f;

        #pragma unroll
        for (int s = 0; s < 4; s++) {
            uint32_t bfr[8][2];
            #pragma unroll
            for (int nt = 0; nt < 4; nt++) {
                const int r = nt * 16 + (mi >> 1) * 8 + (lane & 7);
                const int c = 2 * s + (mi & 1);
                ldsm_x4(bfr[2*nt][0], bfr[2*nt][1], bfr[2*nt+1][0], bfr[2*nt+1][1],
                        ko + r * 128 + ((c ^ (r & 7)) * 16));
            }
            #pragma unroll
            for (int mt = 0; mt < 2; mt++)
                #pragma unroll
                for (int n = 0; n < 8; n++)
                    mma_f16(sc[mt][n], qa[s][mt], bfr[n][0], bfr[n][1]);
        }

        uint32_t vf0[8][2];
        #pragma unroll
        for (int nt = 0; nt < 4; nt++) {
            const int r = (mi & 1) * 8 + (lane & 7);
            const int c = 2 * nt + (mi >> 1);
            ldsm_x4t(vf0[2*nt][0], vf0[2*nt][1], vf0[2*nt+1][0], vf0[2*nt+1][1],
                     vo + r * 128 + ((c ^ (r & 7)) * 16));
        }

        if (kt * 64 + 63 > wrow) {
            #pragma unroll
            for (int mt = 0; mt < 2; mt++) {
                const int r0 = wrow + mt * 16 + gg;
                const int r1 = r0 + 8;
                #pragma unroll
                for (int n = 0; n < 8; n++) {
                    const int col = kt * 64 + n * 8 + tg * 2;
                    if (col     > r0) sc[mt][n][0] = -1e30f;
                    if (col + 1 > r0) sc[mt][n][1] = -1e30f;
                    if (col     > r1) sc[mt][n][2] = -1e30f;
                    if (col + 1 > r1) sc[mt][n][3] = -1e30f;
                }
            }
        }

        uint32_t pa[2][4][4];
        #pragma unroll
        for (int mt = 0; mt < 2; mt++) {
            float mx0 = -1e30f, mx1 = -1e30f;
            #pragma unroll
            for (int n = 0; n < 8; n++) {
                mx0 = fmaxf(mx0, fmaxf(sc[mt][n][0], sc[mt][n][1]));
                mx1 = fmaxf(mx1, fmaxf(sc[mt][n][2], sc[mt][n][3]));
            }
            mx0 = fmaxf(mx0, __shfl_xor_sync(0xffffffffu, mx0, 1));
            mx0 = fmaxf(mx0, __shfl_xor_sync(0xffffffffu, mx0, 2));
            mx1 = fmaxf(mx1, __shfl_xor_sync(0xffffffffu, mx1, 1));
            mx1 = fmaxf(mx1, __shfl_xor_sync(0xffffffffu, mx1, 2));
            const float mn0 = fmaxf(mM[mt][0], mx0);
            const float mn1 = fmaxf(mM[mt][1], mx1);
            const float c0 = exp2f(mM[mt][0] - mn0);
            const float c1 = exp2f(mM[mt][1] - mn1);
            mM[mt][0] = mn0; mM[mt][1] = mn1;

            #pragma unroll
            for (int s = 0; s < 4; s++) {
                pa[mt][s][0] = h2exp2(packh2(sc[mt][2*s][0]   - mn0, sc[mt][2*s][1]   - mn0));
                pa[mt][s][1] = h2exp2(packh2(sc[mt][2*s][2]   - mn1, sc[mt][2*s][3]   - mn1));
                pa[mt][s][2] = h2exp2(packh2(sc[mt][2*s+1][0] - mn0, sc[mt][2*s+1][1] - mn0));
                pa[mt][s][3] = h2exp2(packh2(sc[mt][2*s+1][2] - mn1, sc[mt][2*s+1][3] - mn1));
            }

            float lacc[4] = {0.f, 0.f, 0.f, 0.f};
            #pragma unroll
            for (int s = 0; s < 4; s++)
                mma_f16(lacc, pa[mt][s], ONES2, ONES2);
            lL[mt][0] = lL[mt][0] * c0 + lacc[0];
            lL[mt][1] = lL[mt][1] * c1 + lacc[2];

            #pragma unroll
            for (int n = 0; n < 8; n++) {
                o[mt][n][0] *= c0; o[mt][n][1] *= c0;
                o[mt][n][2] *= c1; o[mt][n][3] *= c1;
            }
        }

        #pragma unroll
        for (int mt = 0; mt < 2; mt++)
            #pragma unroll
            for (int n = 0; n < 8; n++)
                mma_f16(o[mt][n], pa[mt][0], vf0[n][0], vf0[n][1]);

        #pragma unroll
        for (int s = 1; s < 4; s++) {
            uint32_t vfr[8][2];
            #pragma unroll
            for (int nt = 0; nt < 4; nt++) {
                const int r = s * 16 + (mi & 1) * 8 + (lane & 7);
                const int c = 2 * nt + (mi >> 1);
                ldsm_x4t(vfr[2*nt][0], vfr[2*nt][1], vfr[2*nt+1][0], vfr[2*nt+1][1],
                         vo + r * 128 + ((c ^ (r & 7)) * 16));
            }
            #pragma unroll
            for (int mt = 0; mt < 2; mt++)
                #pragma unroll
                for (int n = 0; n < 8; n++)
                    mma_f16(o[mt][n], pa[mt][s], vfr[n][0], vfr[n][1]);
        }

        if (kt + 2 < KT) { loadKV(kt + 2); CPCOMMIT(); }
    }

    #pragma unroll
    for (int mt = 0; mt < 2; mt++) {
        const float i0 = 1.f / lL[mt][0], i1 = 1.f / lL[mt][1];
        const int r0 = wrow + mt * 16 + gg;
        const int r1 = r0 + 8;
        #pragma unroll
        for (int n = 0; n < 8; n++) {
            const int col = h * 64 + n * 8 + tg * 2;
            *(uint32_t*)(obuf + (size_t)r0 * D_MODEL + col) =
                packh2(o[mt][n][0] * i0, o[mt][n][1] * i0);
            *(uint32_t*)(obuf + (size_t)r1 * D_MODEL + col) =
                packh2(o[mt][n][2] * i1, o[mt][n][3] * i1);
        }
    }
}

// ---------------------------------------------------------------------------
// fused flash + O-projection.  grid = 768:
//   bid 0..511   : flash, qt = 15 - bid/32 (longest first), h = bid % 32
//   bid 512..767 : gemm_o tile; spins until its qt's 32 flash CTAs are done
// ---------------------------------------------------------------------------
__global__ __launch_bounds__(128, 2)
void flash_o(const __half* __restrict__ qbuf, const __half* __restrict__ kbuf,
             const __half* __restrict__ vbuf, __half* __restrict__ abuf,
             const __half* __restrict__ WO, const float* __restrict__ bo,
             float* __restrict__ out)
{
    extern __shared__ char sm[];
    const int bid = blockIdx.x;
    if (bid < 512) {
        const int qt = 15 - (bid >> 5);
        const int h  = bid & 31;
        flash_body(qbuf, kbuf, vbuf, abuf, qt, h, sm);
        __syncthreads();
        if (threadIdx.x == 0) {
            __threadfence();
            atomicAdd(&g_cnt[qt], 1);
        }
    } else {
        const int t  = bid - 512;
        const int qi = t >> 4;             // m-tile / qt index (ascending)
        const int n0 = (t & 15) * 128;
        if (threadIdx.x == 0) {
            while (atomicAdd(&g_cnt[qi], 0) < 32)
                __nanosleep(64);
        }
        __syncthreads();
        __threadfence();
        gemm_body<0>(abuf, WO, bo, out, D_MODEL, qi * 128, n0, smem_u32(sm));
    }
}

// ---------------------------------------------------------------------------
// Launch
// ---------------------------------------------------------------------------
extern "C" void kernel_launch(void* const* d_in, const int* in_sizes, int n_in,
                              void* d_out, int out_size)
{
    const float* queries = (const float*)d_in[0];
    const float* keys    = (const float*)d_in[1];
    const float* values  = (const float*)d_in[2];
    const float* Wq      = (const float*)d_in[3];
    const float* bq      = (const float*)d_in[4];
    const float* Wk      = (const float*)d_in[5];
    const float* bk      = (const float*)d_in[6];
    const float* Wv      = (const float*)d_in[7];
    const float* bv      = (const float*)d_in[8];
    const float* Wo      = (const float*)d_in[9];
    const float* bo      = (const float*)d_in[10];
    float*       out     = (float*)d_out;

    __half *qh, *kh, *vh, *ah, *bh, *ch, *wq, *wk, *wv, *wo;
    cudaGetSymbolAddress((void**)&qh, g_qh);
    cudaGetSymbolAddress((void**)&kh, g_kh);
    cudaGetSymbolAddress((void**)&vh, g_vh);
    cudaGetSymbolAddress((void**)&ah, g_ah);
    cudaGetSymbolAddress((void**)&bh, g_bh);
    cudaGetSymbolAddress((void**)&ch, g_ch);
    cudaGetSymbolAddress((void**)&wq, g_wq);
    cudaGetSymbolAddress((void**)&wk, g_wk);
    cudaGetSymbolAddress((void**)&wv, g_wv);
    cudaGetSymbolAddress((void**)&wo, g_wo);

    cudaFuncSetAttribute(gemm_qkv, cudaFuncAttributeMaxDynamicSharedMemorySize, 3 * GSTAGE);
    cudaFuncSetAttribute(flash_o,  cudaFuncAttributeMaxDynamicSharedMemorySize, 3 * GSTAGE);

    // prep (also zeroes flash->gemm counters)
    prep<<<dim3(64, 64, 7), 256>>>(
        Wq, Wk, Wv, Wo,
        (const float4*)queries, (const float4*)keys, (const float4*)values,
        wq, wk, wv, wo, ah, bh, ch);

    // Q + K + V projections fused
    gemm_qkv<<<dim3(24, S_LEN / 128), 128, 3 * GSTAGE>>>(
        ah, bh, ch, wq, wk, wv, bq, bk, bv, qh, kh, vh);

    // fused: causal GQA flash attention + output projection
    flash_o<<<768, 128, 3 * GSTAGE>>>(qh, kh, vh, ah, wo, bo, out);
}